// round 2
// baseline (speedup 1.0000x reference)
#include <cuda_runtime.h>

#define NG 3
#define PP 8
#define BB 8
#define CCH 128
#define SSQ 1024
#define LLQ 64
#define HH 4
#define DH 32
#define SCALE_F 0.17677669529663687f

// Scratch (static __device__ arrays: allocation-free per harness rules)
__device__ __align__(256) float g_k[NG*BB*CCH*SSQ];     // [g][b][i][s]
__device__ __align__(256) float g_v[NG*BB*CCH*SSQ];     // [g][b][i][s]
__device__ __align__(256) float g_q[NG*PP*LLQ*CCH];     // [g][p][l][i]
__device__ __align__(256) float g_heat[NG*BB*PP*SSQ];   // [g][b][p][s]
__device__ float g_dist[NG*BB*PP];                      // [g][b][p]

// ---------------------------------------------------------------------------
__global__ void zero_kernel() {
    int i = blockIdx.x * 256 + threadIdx.x;
    if (i < NG*BB*PP*SSQ) g_heat[i] = 0.f;
    if (i < NG*BB*PP)     g_dist[i] = 0.f;
}

// ---------------------------------------------------------------------------
// K/V projection: KT[g][b][i][s] = sum_c w[g][i][c] * x[b][c][s]
// grid (16 s-tiles, 2 i-tiles, 24 g*b), 256 threads, 64x64 output tile, both K and V.
__global__ void proj_kv_kernel(const float* __restrict__ x,
                               const float* __restrict__ kw,
                               const float* __restrict__ vw) {
    __shared__ float Xs[16][65];
    __shared__ float Wk[64][17];
    __shared__ float Wv[64][17];
    int g = blockIdx.z >> 3, b = blockIdx.z & 7;
    int i0 = blockIdx.y * 64, s0 = blockIdx.x * 64;
    int tid = threadIdx.x;
    int tx = tid & 15, ty = tid >> 4;
    float aK[4][4] = {}, aV[4][4] = {};
    const float* xb  = x  + (size_t)b * CCH * SSQ;
    const float* kwg = kw + (size_t)g * CCH * CCH;
    const float* vwg = vw + (size_t)g * CCH * CCH;

    for (int c0 = 0; c0 < CCH; c0 += 16) {
        #pragma unroll
        for (int r = 0; r < 4; r++) {
            int id = tid + 256 * r;           // 0..1023
            int cc = id >> 6, ss = id & 63;
            Xs[cc][ss] = xb[(size_t)(c0 + cc) * SSQ + s0 + ss];
        }
        #pragma unroll
        for (int r = 0; r < 4; r++) {
            int id = tid + 256 * r;           // 0..1023
            int ii = id >> 4, cc = id & 15;
            Wk[ii][cc] = kwg[(i0 + ii) * CCH + c0 + cc];
            Wv[ii][cc] = vwg[(i0 + ii) * CCH + c0 + cc];
        }
        __syncthreads();
        #pragma unroll
        for (int c = 0; c < 16; c++) {
            float xv[4], kv[4], vv[4];
            #pragma unroll
            for (int j = 0; j < 4; j++) xv[j] = Xs[c][tx*4 + j];
            #pragma unroll
            for (int a = 0; a < 4; a++) { kv[a] = Wk[ty*4 + a][c]; vv[a] = Wv[ty*4 + a][c]; }
            #pragma unroll
            for (int a = 0; a < 4; a++)
                #pragma unroll
                for (int j = 0; j < 4; j++) {
                    aK[a][j] += kv[a] * xv[j];
                    aV[a][j] += vv[a] * xv[j];
                }
        }
        __syncthreads();
    }
    float* kout = g_k + (size_t)(g*BB + b) * CCH * SSQ;
    float* vout = g_v + (size_t)(g*BB + b) * CCH * SSQ;
    #pragma unroll
    for (int a = 0; a < 4; a++)
        #pragma unroll
        for (int j = 0; j < 4; j++) {
            kout[(size_t)(i0 + ty*4 + a) * SSQ + s0 + tx*4 + j] = aK[a][j];
            vout[(size_t)(i0 + ty*4 + a) * SSQ + s0 + tx*4 + j] = aV[a][j];
        }
}

// ---------------------------------------------------------------------------
// Q projection: q_proj[g][p][l][i] = sum_c proto[g*8+p][c][l] * qw[g][i][c]
// grid 24 (g*p), 256 threads.
__global__ void proj_q_kernel(const float* __restrict__ proto,
                              const float* __restrict__ qw) {
    __shared__ float Ps[CCH][LLQ];   // 32 KB  [c][l]
    __shared__ float Ws[CCH][17];    // chunked W: [i][cc]
    int g = blockIdx.x >> 3, p = blockIdx.x & 7;
    int tid = threadIdx.x;
    const float* pg  = proto + (size_t)(g*PP + p) * CCH * LLQ;
    const float* qwg = qw + (size_t)g * CCH * CCH;

    for (int r = 0; r < 32; r++) {
        int id = tid + 256 * r;       // 0..8191
        Ps[id >> 6][id & 63] = pg[id];
    }
    __syncthreads();

    int l = tid & 63;
    int ibase = tid >> 6;             // 0..3
    float acc[32];
    #pragma unroll
    for (int r = 0; r < 32; r++) acc[r] = 0.f;

    for (int c0 = 0; c0 < CCH; c0 += 16) {
        #pragma unroll
        for (int r = 0; r < 8; r++) {
            int id = tid + 256 * r;   // 0..2047
            Ws[id >> 4][id & 15] = qwg[(id >> 4) * CCH + c0 + (id & 15)];
        }
        __syncthreads();
        float pc[16];
        #pragma unroll
        for (int cc = 0; cc < 16; cc++) pc[cc] = Ps[c0 + cc][l];
        #pragma unroll
        for (int r = 0; r < 32; r++) {
            int i = ibase + 4 * r;
            float a = acc[r];
            #pragma unroll
            for (int cc = 0; cc < 16; cc++) a += Ws[i][cc] * pc[cc];
            acc[r] = a;
        }
        __syncthreads();
    }
    float* qo = g_q + (size_t)(g*PP + p) * LLQ * CCH;
    #pragma unroll
    for (int r = 0; r < 32; r++) qo[l * CCH + ibase + 4*r] = acc[r];
}

// ---------------------------------------------------------------------------
// Attention: one CTA per (g,b,h,p). L in 2 chunks of 32 rows.
// Dyn smem: q_s(2048) + D(32*1024) + KV(32*132) + heat(1024) + red(64) floats.
#define SM_Q    0
#define SM_D    2048
#define SM_KV   (2048 + 32768)
#define SM_HEAT (2048 + 32768 + 4224)
#define SM_RED  (2048 + 32768 + 4224 + 1024)
#define SM_FLOATS (2048 + 32768 + 4224 + 1024 + 64)
#define SM_BYTES (SM_FLOATS * 4)

__global__ void __launch_bounds__(256, 1) attn_kernel() {
    extern __shared__ float sm[];
    float* q_s    = sm + SM_Q;      // [64][32]
    float* D      = sm + SM_D;      // [32][1024]
    float* KV     = sm + SM_KV;     // [32][132]
    float* heat_s = sm + SM_HEAT;   // [1024]
    float* red    = sm + SM_RED;

    int idx = blockIdx.x;
    int p = idx & 7, h = (idx >> 3) & 3, b = (idx >> 5) & 7, g = idx >> 8;
    int tid = threadIdx.x, lane = tid & 31, w = tid >> 5;

    const float* Kg = g_k + ((size_t)((g*BB + b) * CCH) + h * DH) * SSQ;
    const float* Vg = g_v + ((size_t)((g*BB + b) * CCH) + h * DH) * SSQ;
    const float* Qg = g_q + (size_t)(g*PP + p) * LLQ * CCH;

    // load q (unscaled; also reused for dist)
    #pragma unroll
    for (int r = 0; r < 8; r++) {
        int id = tid + 256 * r;       // 0..2047
        int l = id >> 5, d = id & 31;
        q_s[id] = Qg[l * CCH + h * DH + d];
    }
    #pragma unroll
    for (int r = 0; r < 4; r++) heat_s[tid + 256 * r] = 0.f;
    float dist_acc = 0.f;
    __syncthreads();

    for (int lc = 0; lc < 2; lc++) {
        int lbase = lc * 32;
        int r0 = 4 * w;                           // warp owns local rows r0..r0+3

        // ---- dots: D[lr][s] = SCALE * q . k ----
        for (int st = 0; st < 8; st++) {
            __syncthreads();
            #pragma unroll
            for (int r = 0; r < 4; r++) {
                int id4 = tid + 256 * r;          // 0..1023 float4s
                int rr = id4 >> 5, c4 = id4 & 31;
                *(float4*)&KV[rr * 132 + c4 * 4] =
                    *(const float4*)&Kg[(size_t)rr * SSQ + st * 128 + c4 * 4];
            }
            __syncthreads();
            float acc[4][4] = {};
            const float* qr = q_s + (lbase + r0) * DH;
            #pragma unroll
            for (int d = 0; d < 32; d++) {
                float4 kv = *(const float4*)&KV[d * 132 + lane * 4];
                float q0 = qr[d], q1 = qr[32 + d], q2 = qr[64 + d], q3 = qr[96 + d];
                acc[0][0] += q0 * kv.x; acc[0][1] += q0 * kv.y;
                acc[0][2] += q0 * kv.z; acc[0][3] += q0 * kv.w;
                acc[1][0] += q1 * kv.x; acc[1][1] += q1 * kv.y;
                acc[1][2] += q1 * kv.z; acc[1][3] += q1 * kv.w;
                acc[2][0] += q2 * kv.x; acc[2][1] += q2 * kv.y;
                acc[2][2] += q2 * kv.z; acc[2][3] += q2 * kv.w;
                acc[3][0] += q3 * kv.x; acc[3][1] += q3 * kv.y;
                acc[3][2] += q3 * kv.z; acc[3][3] += q3 * kv.w;
            }
            #pragma unroll
            for (int a = 0; a < 4; a++) {
                float4 o;
                o.x = acc[a][0] * SCALE_F; o.y = acc[a][1] * SCALE_F;
                o.z = acc[a][2] * SCALE_F; o.w = acc[a][3] * SCALE_F;
                *(float4*)&D[(r0 + a) * SSQ + st * 128 + lane * 4] = o;
            }
        }
        __syncthreads();

        // ---- softmax over own rows (full S) ----
        #pragma unroll
        for (int a = 0; a < 4; a++) {
            float* row = D + (r0 + a) * SSQ;
            float m = -1e30f;
            for (int j = lane; j < SSQ; j += 32) m = fmaxf(m, row[j]);
            #pragma unroll
            for (int o = 16; o; o >>= 1) m = fmaxf(m, __shfl_xor_sync(0xffffffffu, m, o));
            float sum = 0.f;
            for (int j = lane; j < SSQ; j += 32) {
                float e = __expf(row[j] - m);
                row[j] = e; sum += e;
            }
            #pragma unroll
            for (int o = 16; o; o >>= 1) sum += __shfl_xor_sync(0xffffffffu, sum, o);
            float inv = 1.f / sum;
            for (int j = lane; j < SSQ; j += 32) row[j] *= inv;
        }
        __syncthreads();

        // ---- heat: sum attn over the 32 chunk rows ----
        #pragma unroll
        for (int jj = 0; jj < 4; jj++) {
            int s = tid + 256 * jj;
            float hs = 0.f;
            #pragma unroll
            for (int r = 0; r < 32; r++) hs += D[r * SSQ + s];
            heat_s[s] += hs;
        }

        // ---- out = attn @ V^T : 2 rows x 2 d per thread, kept in regs ----
        int lrA = w * 4 + ((lane >> 4) << 1);
        int lrB = lrA + 1;
        int d0 = lane & 15, d1 = d0 + 16;
        float a00 = 0.f, a01 = 0.f, a10 = 0.f, a11 = 0.f;
        for (int st = 0; st < 8; st++) {
            __syncthreads();
            #pragma unroll
            for (int r = 0; r < 4; r++) {
                int id4 = tid + 256 * r;
                int rr = id4 >> 5, c4 = id4 & 31;
                *(float4*)&KV[rr * 132 + c4 * 4] =
                    *(const float4*)&Vg[(size_t)rr * SSQ + st * 128 + c4 * 4];
            }
            __syncthreads();
            const float* rowA = D + lrA * SSQ + st * 128;
            const float* rowB = D + lrB * SSQ + st * 128;
            const float* v0 = KV + d0 * 132;
            const float* v1 = KV + d1 * 132;
            #pragma unroll
            for (int ss = 0; ss < 128; ss += 4) {
                float4 pa  = *(const float4*)&rowA[ss];
                float4 pb  = *(const float4*)&rowB[ss];
                float4 vv0 = *(const float4*)&v0[ss];
                float4 vv1 = *(const float4*)&v1[ss];
                a00 += pa.x*vv0.x + pa.y*vv0.y + pa.z*vv0.z + pa.w*vv0.w;
                a01 += pa.x*vv1.x + pa.y*vv1.y + pa.z*vv1.z + pa.w*vv1.w;
                a10 += pb.x*vv0.x + pb.y*vv0.y + pb.z*vv0.z + pb.w*vv0.w;
                a11 += pb.x*vv1.x + pb.y*vv1.y + pb.z*vv1.z + pb.w*vv1.w;
            }
        }
        // dist contributions (q_proj - out)^2 for this head slice
        {
            int lA = lbase + lrA, lB = lbase + lrB;
            float e;
            e = q_s[lA * DH + d0] - a00; dist_acc += e * e;
            e = q_s[lA * DH + d1] - a01; dist_acc += e * e;
            e = q_s[lB * DH + d0] - a10; dist_acc += e * e;
            e = q_s[lB * DH + d1] - a11; dist_acc += e * e;
        }
    }
    __syncthreads();

    // heat -> global (summed over h via atomics)
    float* hout = g_heat + (size_t)((g*BB + b) * PP + p) * SSQ;
    #pragma unroll
    for (int jj = 0; jj < 4; jj++) {
        int s = tid + 256 * jj;
        atomicAdd(&hout[s], heat_s[s]);
    }
    // dist -> global
    #pragma unroll
    for (int o = 16; o; o >>= 1) dist_acc += __shfl_xor_sync(0xffffffffu, dist_acc, o);
    if (lane == 0) red[w] = dist_acc;
    __syncthreads();
    if (w == 0) {
        float v = (lane < 8) ? red[lane] : 0.f;
        #pragma unroll
        for (int o = 4; o; o >>= 1) v += __shfl_xor_sync(0xffffffffu, v, o);
        if (lane == 0) atomicAdd(&g_dist[(g*BB + b) * PP + p], v);
    }
}

// ---------------------------------------------------------------------------
// Finalize: dist/(64*128) and argmax(heat) -> out = [dist(8x24) | idx(8x24)]
__global__ void finalize_kernel(float* __restrict__ out, int out_size) {
    __shared__ float bv[128];
    __shared__ int  bidx[128];
    int gbp = blockIdx.x;             // = (g*8+b)*8+p
    int tid = threadIdx.x;
    const float* hrow = g_heat + (size_t)gbp * SSQ;
    float best = -1e30f; int bi = 0;
    for (int j = tid; j < SSQ; j += 128) {
        float v = hrow[j];
        if (v > best) { best = v; bi = j; }
    }
    bv[tid] = best; bidx[tid] = bi;
    __syncthreads();
    for (int s = 64; s; s >>= 1) {
        if (tid < s) {
            if (bv[tid + s] > bv[tid] ||
                (bv[tid + s] == bv[tid] && bidx[tid + s] < bidx[tid])) {
                bv[tid] = bv[tid + s]; bidx[tid] = bidx[tid + s];
            }
        }
        __syncthreads();
    }
    if (tid == 0) {
        int g = gbp >> 6, b = (gbp >> 3) & 7, p = gbp & 7;
        int col = g * PP + p;
        out[b * 24 + col] = g_dist[gbp] * (1.f / (64.f * 128.f));
        if (out_size >= 384)
            out[192 + b * 24 + col] = (float)bidx[0];
    }
}

// ---------------------------------------------------------------------------
extern "C" void kernel_launch(void* const* d_in, const int* in_sizes, int n_in,
                              void* d_out, int out_size) {
    const float* x     = (const float*)d_in[0];
    const float* proto = (const float*)d_in[1];
    const float* qw    = (const float*)d_in[2];
    const float* kw    = (const float*)d_in[3];
    const float* vw    = (const float*)d_in[4];
    float* out = (float*)d_out;

    cudaFuncSetAttribute(attn_kernel,
                         cudaFuncAttributeMaxDynamicSharedMemorySize, SM_BYTES);

    zero_kernel<<<768, 256>>>();
    proj_kv_kernel<<<dim3(16, 2, 24), 256>>>(x, kw, vw);
    proj_q_kernel<<<24, 256>>>(proto, qw);
    attn_kernel<<<768, 256, SM_BYTES>>>();
    finalize_kernel<<<192, 128>>>(out, out_size);
}

// round 3
// speedup vs baseline: 1.3878x; 1.3878x over previous
#include <cuda_runtime.h>
#include <cuda_fp16.h>
#include <cstdint>

#define NG 3
#define PP 8
#define BB 8
#define CCH 128
#define SSQ 1024
#define LLQ 64
#define HH 4
#define DH 32
#define SCALE_F 0.17677669529663687f

// Scratch (static __device__ arrays: allocation-free per harness rules)
__device__ __align__(256) float g_k[NG*BB*CCH*SSQ];     // [g][b][i][s]
__device__ __align__(256) float g_v[NG*BB*CCH*SSQ];     // [g][b][i][s]
__device__ __align__(256) float g_q[NG*PP*LLQ*CCH];     // [g][p][l][i]
__device__ __align__(256) float g_heat[NG*BB*PP*SSQ];   // [g][b][p][s]
__device__ float g_dist[NG*BB*PP];                      // [g][b][p]

// ---------------------------------------------------------------------------
__global__ void zero_kernel() {
    int i = blockIdx.x * 256 + threadIdx.x;
    if (i < NG*BB*PP*SSQ) g_heat[i] = 0.f;
    if (i < NG*BB*PP)     g_dist[i] = 0.f;
}

// ---------------------------------------------------------------------------
// K/V projection: KT[g][b][i][s] = sum_c w[g][i][c] * x[b][c][s]
__global__ void proj_kv_kernel(const float* __restrict__ x,
                               const float* __restrict__ kw,
                               const float* __restrict__ vw) {
    __shared__ float Xs[16][65];
    __shared__ float Wk[64][17];
    __shared__ float Wv[64][17];
    int g = blockIdx.z >> 3, b = blockIdx.z & 7;
    int i0 = blockIdx.y * 64, s0 = blockIdx.x * 64;
    int tid = threadIdx.x;
    int tx = tid & 15, ty = tid >> 4;
    float aK[4][4] = {}, aV[4][4] = {};
    const float* xb  = x  + (size_t)b * CCH * SSQ;
    const float* kwg = kw + (size_t)g * CCH * CCH;
    const float* vwg = vw + (size_t)g * CCH * CCH;

    for (int c0 = 0; c0 < CCH; c0 += 16) {
        #pragma unroll
        for (int r = 0; r < 4; r++) {
            int id = tid + 256 * r;
            int cc = id >> 6, ss = id & 63;
            Xs[cc][ss] = xb[(size_t)(c0 + cc) * SSQ + s0 + ss];
        }
        #pragma unroll
        for (int r = 0; r < 4; r++) {
            int id = tid + 256 * r;
            int ii = id >> 4, cc = id & 15;
            Wk[ii][cc] = kwg[(i0 + ii) * CCH + c0 + cc];
            Wv[ii][cc] = vwg[(i0 + ii) * CCH + c0 + cc];
        }
        __syncthreads();
        #pragma unroll
        for (int c = 0; c < 16; c++) {
            float xv[4], kv[4], vv[4];
            #pragma unroll
            for (int j = 0; j < 4; j++) xv[j] = Xs[c][tx*4 + j];
            #pragma unroll
            for (int a = 0; a < 4; a++) { kv[a] = Wk[ty*4 + a][c]; vv[a] = Wv[ty*4 + a][c]; }
            #pragma unroll
            for (int a = 0; a < 4; a++)
                #pragma unroll
                for (int j = 0; j < 4; j++) {
                    aK[a][j] += kv[a] * xv[j];
                    aV[a][j] += vv[a] * xv[j];
                }
        }
        __syncthreads();
    }
    float* kout = g_k + (size_t)(g*BB + b) * CCH * SSQ;
    float* vout = g_v + (size_t)(g*BB + b) * CCH * SSQ;
    #pragma unroll
    for (int a = 0; a < 4; a++)
        #pragma unroll
        for (int j = 0; j < 4; j++) {
            kout[(size_t)(i0 + ty*4 + a) * SSQ + s0 + tx*4 + j] = aK[a][j];
            vout[(size_t)(i0 + ty*4 + a) * SSQ + s0 + tx*4 + j] = aV[a][j];
        }
}

// ---------------------------------------------------------------------------
// Q projection: q_proj[g][p][l][i] = sum_c proto[g*8+p][c][l] * qw[g][i][c]
__global__ void proj_q_kernel(const float* __restrict__ proto,
                              const float* __restrict__ qw) {
    __shared__ float Ps[CCH][LLQ];
    __shared__ float Ws[CCH][17];
    int g = blockIdx.x >> 3, p = blockIdx.x & 7;
    int tid = threadIdx.x;
    const float* pg  = proto + (size_t)(g*PP + p) * CCH * LLQ;
    const float* qwg = qw + (size_t)g * CCH * CCH;

    for (int r = 0; r < 32; r++) {
        int id = tid + 256 * r;
        Ps[id >> 6][id & 63] = pg[id];
    }
    __syncthreads();

    int l = tid & 63;
    int ibase = tid >> 6;
    float acc[32];
    #pragma unroll
    for (int r = 0; r < 32; r++) acc[r] = 0.f;

    for (int c0 = 0; c0 < CCH; c0 += 16) {
        #pragma unroll
        for (int r = 0; r < 8; r++) {
            int id = tid + 256 * r;
            Ws[id >> 4][id & 15] = qwg[(id >> 4) * CCH + c0 + (id & 15)];
        }
        __syncthreads();
        float pc[16];
        #pragma unroll
        for (int cc = 0; cc < 16; cc++) pc[cc] = Ps[c0 + cc][l];
        #pragma unroll
        for (int r = 0; r < 32; r++) {
            int i = ibase + 4 * r;
            float a = acc[r];
            #pragma unroll
            for (int cc = 0; cc < 16; cc++) a += Ws[i][cc] * pc[cc];
            acc[r] = a;
        }
        __syncthreads();
    }
    float* qo = g_q + (size_t)(g*PP + p) * LLQ * CCH;
    #pragma unroll
    for (int r = 0; r < 32; r++) qo[l * CCH + ibase + 4*r] = acc[r];
}

// ---------------------------------------------------------------------------
// Attention v2: one CTA per (g,b,h,p,lc); 32 L-rows per CTA; 2 CTAs/SM.
// exp computed without max-subtraction (numerically safe: |score| < ~3).
// Exp-scores stored in fp16 (E); row sums Z accumulated in registers during QK.
//
// smem layout (bytes):
//   KV   : [32][132] fp32          @ 0       (16896)
//   q_s  : [32][32]  fp32          @ 16896   (4096)
//   E    : [32][1032] half         @ 20992   (66048)
//   invZ : [32] fp32               @ 87040   (128)
//   red  : [64] fp32               @ 87168   (256)
#define SMB_KV    0
#define SMB_Q     16896
#define SMB_E     20992
#define SMB_IZ    87040
#define SMB_RED   87168
#define SMB_TOTAL 87424
#define ESTRIDE   1032

__global__ void __launch_bounds__(256, 2) attn_kernel() {
    extern __shared__ char smraw[];
    float* KV     = (float*)(smraw + SMB_KV);
    float* q_s    = (float*)(smraw + SMB_Q);
    __half* Eh    = (__half*)(smraw + SMB_E);
    float* invZ_s = (float*)(smraw + SMB_IZ);
    float* red    = (float*)(smraw + SMB_RED);

    int idx = blockIdx.x;                   // 1536 = g(3) b(8) h(4) p(8) lc(2)
    int lc = idx & 1, p = (idx >> 1) & 7, h = (idx >> 4) & 3,
        b = (idx >> 6) & 7, g = idx >> 9;
    int tid = threadIdx.x, lane = tid & 31, w = tid >> 5;
    int lbase = lc * 32;

    const float* Kg = g_k + ((size_t)((g*BB + b) * CCH) + h * DH) * SSQ;
    const float* Vg = g_v + ((size_t)((g*BB + b) * CCH) + h * DH) * SSQ;
    const float* Qg = g_q + (size_t)(g*PP + p) * LLQ * CCH;

    // load q rows for this chunk: [32 rows][32 d]
    #pragma unroll
    for (int r = 0; r < 4; r++) {
        int id = tid + 256 * r;             // 0..1023
        int row = id >> 5, d = id & 31;
        q_s[id] = Qg[(lbase + row) * CCH + h * DH + d];
    }
    __syncthreads();

    int r0 = 4 * w;                         // warp owns rows r0..r0+3
    float zpart[4] = {0.f, 0.f, 0.f, 0.f};

    // ================= QK + exp + fp16 store =================
    for (int st = 0; st < 8; st++) {
        __syncthreads();
        #pragma unroll
        for (int r = 0; r < 4; r++) {
            int id4 = tid + 256 * r;        // 0..1023 float4 slots
            int rr = id4 >> 5, c4 = id4 & 31;
            *(float4*)&KV[rr * 132 + c4 * 4] =
                *(const float4*)&Kg[(size_t)rr * SSQ + st * 128 + c4 * 4];
        }
        __syncthreads();

        float acc[4][4] = {};
        const float* qr = q_s + r0 * DH;    // 4 rows, stride 32
        #pragma unroll
        for (int d4 = 0; d4 < 8; d4++) {
            float4 kv0 = *(const float4*)&KV[(d4*4 + 0) * 132 + lane * 4];
            float4 kv1 = *(const float4*)&KV[(d4*4 + 1) * 132 + lane * 4];
            float4 kv2 = *(const float4*)&KV[(d4*4 + 2) * 132 + lane * 4];
            float4 kv3 = *(const float4*)&KV[(d4*4 + 3) * 132 + lane * 4];
            #pragma unroll
            for (int a = 0; a < 4; a++) {
                float4 qv = *(const float4*)&qr[a * DH + d4 * 4];
                acc[a][0] += qv.x * kv0.x; acc[a][1] += qv.x * kv0.y;
                acc[a][2] += qv.x * kv0.z; acc[a][3] += qv.x * kv0.w;
                acc[a][0] += qv.y * kv1.x; acc[a][1] += qv.y * kv1.y;
                acc[a][2] += qv.y * kv1.z; acc[a][3] += qv.y * kv1.w;
                acc[a][0] += qv.z * kv2.x; acc[a][1] += qv.z * kv2.y;
                acc[a][2] += qv.z * kv2.z; acc[a][3] += qv.z * kv2.w;
                acc[a][0] += qv.w * kv3.x; acc[a][1] += qv.w * kv3.y;
                acc[a][2] += qv.w * kv3.z; acc[a][3] += qv.w * kv3.w;
            }
        }
        // exp + Z accumulate + fp16 store
        #pragma unroll
        for (int a = 0; a < 4; a++) {
            float e0 = __expf(acc[a][0] * SCALE_F);
            float e1 = __expf(acc[a][1] * SCALE_F);
            float e2 = __expf(acc[a][2] * SCALE_F);
            float e3 = __expf(acc[a][3] * SCALE_F);
            zpart[a] += (e0 + e1) + (e2 + e3);
            __half2 h01 = __floats2half2_rn(e0, e1);
            __half2 h23 = __floats2half2_rn(e2, e3);
            uint2 u;
            u.x = reinterpret_cast<uint32_t&>(h01);
            u.y = reinterpret_cast<uint32_t&>(h23);
            *reinterpret_cast<uint2*>(Eh + (r0 + a) * ESTRIDE + st * 128 + lane * 4) = u;
        }
    }
    // row sums -> invZ
    #pragma unroll
    for (int a = 0; a < 4; a++) {
        float z = zpart[a];
        #pragma unroll
        for (int o = 16; o; o >>= 1) z += __shfl_xor_sync(0xffffffffu, z, o);
        if (lane == 0) invZ_s[r0 + a] = 1.f / z;
    }
    __syncthreads();

    // ================= heat: column sums of normalized attn =================
    float* hout = g_heat + (size_t)((g*BB + b) * PP + p) * SSQ;
    {
        float iz[32];
        #pragma unroll
        for (int r = 0; r < 32; r++) iz[r] = invZ_s[r];
        #pragma unroll
        for (int j = 0; j < 4; j++) {
            int s = tid + 256 * j;
            float hs = 0.f;
            #pragma unroll
            for (int r = 0; r < 32; r++)
                hs += __half2float(Eh[r * ESTRIDE + s]) * iz[r];
            atomicAdd(&hout[s], hs);
        }
    }

    // ================= PV (unnormalized, divide by Z at end) =================
    int lrA = 4 * w + ((lane >> 4) << 1);
    int lrB = lrA + 1;
    int d0 = lane & 15, d1 = d0 + 16;
    float a00 = 0.f, a01 = 0.f, a10 = 0.f, a11 = 0.f;

    for (int st = 0; st < 8; st++) {
        __syncthreads();
        #pragma unroll
        for (int r = 0; r < 4; r++) {
            int id4 = tid + 256 * r;
            int rr = id4 >> 5, c4 = id4 & 31;
            *(float4*)&KV[rr * 132 + c4 * 4] =
                *(const float4*)&Vg[(size_t)rr * SSQ + st * 128 + c4 * 4];
        }
        __syncthreads();

        const __half* rA = Eh + lrA * ESTRIDE + st * 128;
        const __half* rB = Eh + lrB * ESTRIDE + st * 128;
        const float* v0 = KV + d0 * 132;
        const float* v1 = KV + d1 * 132;
        #pragma unroll
        for (int ss = 0; ss < 128; ss += 4) {
            uint2 ua = *reinterpret_cast<const uint2*>(rA + ss);
            uint2 ub = *reinterpret_cast<const uint2*>(rB + ss);
            float2 fa01 = __half22float2(reinterpret_cast<__half2&>(ua.x));
            float2 fa23 = __half22float2(reinterpret_cast<__half2&>(ua.y));
            float2 fb01 = __half22float2(reinterpret_cast<__half2&>(ub.x));
            float2 fb23 = __half22float2(reinterpret_cast<__half2&>(ub.y));
            float4 vv0 = *(const float4*)&v0[ss];
            float4 vv1 = *(const float4*)&v1[ss];
            a00 += fa01.x*vv0.x + fa01.y*vv0.y + fa23.x*vv0.z + fa23.y*vv0.w;
            a01 += fa01.x*vv1.x + fa01.y*vv1.y + fa23.x*vv1.z + fa23.y*vv1.w;
            a10 += fb01.x*vv0.x + fb01.y*vv0.y + fb23.x*vv0.z + fb23.y*vv0.w;
            a11 += fb01.x*vv1.x + fb01.y*vv1.y + fb23.x*vv1.z + fb23.y*vv1.w;
        }
    }

    // normalize + dist contributions
    float izA = invZ_s[lrA], izB = invZ_s[lrB];
    a00 *= izA; a01 *= izA; a10 *= izB; a11 *= izB;
    float dist_acc;
    {
        float e;
        e = q_s[lrA * DH + d0] - a00; dist_acc  = e * e;
        e = q_s[lrA * DH + d1] - a01; dist_acc += e * e;
        e = q_s[lrB * DH + d0] - a10; dist_acc += e * e;
        e = q_s[lrB * DH + d1] - a11; dist_acc += e * e;
    }
    #pragma unroll
    for (int o = 16; o; o >>= 1) dist_acc += __shfl_xor_sync(0xffffffffu, dist_acc, o);
    if (lane == 0) red[w] = dist_acc;
    __syncthreads();
    if (w == 0) {
        float v = (lane < 8) ? red[lane] : 0.f;
        #pragma unroll
        for (int o = 4; o; o >>= 1) v += __shfl_xor_sync(0xffffffffu, v, o);
        if (lane == 0) atomicAdd(&g_dist[(g*BB + b) * PP + p], v);
    }
}

// ---------------------------------------------------------------------------
// Finalize: dist/(64*128) and argmax(heat) -> out = [dist(8x24) | idx(8x24)]
__global__ void finalize_kernel(float* __restrict__ out, int out_size) {
    __shared__ float bv[128];
    __shared__ int  bidx[128];
    int gbp = blockIdx.x;
    int tid = threadIdx.x;
    const float* hrow = g_heat + (size_t)gbp * SSQ;
    float best = -1e30f; int bi = 0;
    for (int j = tid; j < SSQ; j += 128) {
        float v = hrow[j];
        if (v > best) { best = v; bi = j; }
    }
    bv[tid] = best; bidx[tid] = bi;
    __syncthreads();
    for (int s = 64; s; s >>= 1) {
        if (tid < s) {
            if (bv[tid + s] > bv[tid] ||
                (bv[tid + s] == bv[tid] && bidx[tid + s] < bidx[tid])) {
                bv[tid] = bv[tid + s]; bidx[tid] = bidx[tid + s];
            }
        }
        __syncthreads();
    }
    if (tid == 0) {
        int g = gbp >> 6, b = (gbp >> 3) & 7, p = gbp & 7;
        int col = g * PP + p;
        out[b * 24 + col] = g_dist[gbp] * (1.f / (64.f * 128.f));
        if (out_size >= 384)
            out[192 + b * 24 + col] = (float)bidx[0];
    }
}

// ---------------------------------------------------------------------------
extern "C" void kernel_launch(void* const* d_in, const int* in_sizes, int n_in,
                              void* d_out, int out_size) {
    const float* x     = (const float*)d_in[0];
    const float* proto = (const float*)d_in[1];
    const float* qw    = (const float*)d_in[2];
    const float* kw    = (const float*)d_in[3];
    const float* vw    = (const float*)d_in[4];
    float* out = (float*)d_out;

    cudaFuncSetAttribute(attn_kernel,
                         cudaFuncAttributeMaxDynamicSharedMemorySize, SMB_TOTAL);

    zero_kernel<<<768, 256>>>();
    proj_kv_kernel<<<dim3(16, 2, 24), 256>>>(x, kw, vw);
    proj_q_kernel<<<24, 256>>>(proto, qw);
    attn_kernel<<<1536, 256, SMB_TOTAL>>>();
    finalize_kernel<<<192, 128>>>(out, out_size);
}

// round 5
// speedup vs baseline: 2.6705x; 1.9242x over previous
#include <cuda_runtime.h>
#include <cuda_fp16.h>
#include <cstdint>

#define NG 3
#define PP 8
#define BB 8
#define CCH 128
#define SSQ 1024
#define LLQ 64
#define HH 4
#define DH 32
#define SCALE_F 0.17677669529663687f

// Scratch (static __device__ arrays: allocation-free per harness rules)
__device__ __align__(256) __half g_kh[NG*BB*SSQ*CCH];   // [g][b][s][c]  fp16
__device__ __align__(256) __half g_vh[NG*BB*CCH*SSQ];   // [g][b][c][s]  fp16
__device__ __align__(256) float  g_q [NG*PP*LLQ*CCH];   // [g][p][l][i]  fp32
__device__ __align__(256) float  g_heat[NG*BB*PP*SSQ];  // [g][b][p][s]
__device__ float g_dist[NG*BB*PP];                      // [g][b][p]

// ---------------------------------------------------------------------------
__global__ void zero_kernel() {
    int i = blockIdx.x * 256 + threadIdx.x;
    if (i < NG*BB*PP*SSQ) g_heat[i] = 0.f;
    if (i < NG*BB*PP)     g_dist[i] = 0.f;
}

// ---------------------------------------------------------------------------
// K/V projection: K[g][b][s][i] (fp16), V[g][b][i][s] (fp16)
__global__ void proj_kv_kernel(const float* __restrict__ x,
                               const float* __restrict__ kw,
                               const float* __restrict__ vw) {
    __shared__ float Xs[16][65];
    __shared__ float Wk[64][17];
    __shared__ float Wv[64][17];
    int g = blockIdx.z >> 3, b = blockIdx.z & 7;
    int i0 = blockIdx.y * 64, s0 = blockIdx.x * 64;
    int tid = threadIdx.x;
    int tx = tid & 15, ty = tid >> 4;
    float aK[4][4] = {}, aV[4][4] = {};
    const float* xb  = x  + (size_t)b * CCH * SSQ;
    const float* kwg = kw + (size_t)g * CCH * CCH;
    const float* vwg = vw + (size_t)g * CCH * CCH;

    for (int c0 = 0; c0 < CCH; c0 += 16) {
        #pragma unroll
        for (int r = 0; r < 4; r++) {
            int id = tid + 256 * r;
            int cc = id >> 6, ss = id & 63;
            Xs[cc][ss] = xb[(size_t)(c0 + cc) * SSQ + s0 + ss];
        }
        #pragma unroll
        for (int r = 0; r < 4; r++) {
            int id = tid + 256 * r;
            int ii = id >> 4, cc = id & 15;
            Wk[ii][cc] = kwg[(i0 + ii) * CCH + c0 + cc];
            Wv[ii][cc] = vwg[(i0 + ii) * CCH + c0 + cc];
        }
        __syncthreads();
        #pragma unroll
        for (int c = 0; c < 16; c++) {
            float xv[4], kv[4], vv[4];
            #pragma unroll
            for (int j = 0; j < 4; j++) xv[j] = Xs[c][tx*4 + j];
            #pragma unroll
            for (int a = 0; a < 4; a++) { kv[a] = Wk[ty*4 + a][c]; vv[a] = Wv[ty*4 + a][c]; }
            #pragma unroll
            for (int a = 0; a < 4; a++)
                #pragma unroll
                for (int j = 0; j < 4; j++) {
                    aK[a][j] += kv[a] * xv[j];
                    aV[a][j] += vv[a] * xv[j];
                }
        }
        __syncthreads();
    }
    // K out: [s][i] fp16, pack half2 along i
    __half* kout = g_kh + (size_t)(g*BB + b) * SSQ * CCH;
    __half* vout = g_vh + (size_t)(g*BB + b) * CCH * SSQ;
    #pragma unroll
    for (int j = 0; j < 4; j++) {
        int s = s0 + tx*4 + j;
        #pragma unroll
        for (int a2 = 0; a2 < 2; a2++) {
            __half2 h = __floats2half2_rn(aK[a2*2][j], aK[a2*2+1][j]);
            *(__half2*)&kout[(size_t)s * CCH + i0 + ty*4 + a2*2] = h;
        }
    }
    // V out: [i][s] fp16, pack half2 along s
    #pragma unroll
    for (int a = 0; a < 4; a++) {
        int i = i0 + ty*4 + a;
        #pragma unroll
        for (int j2 = 0; j2 < 2; j2++) {
            __half2 h = __floats2half2_rn(aV[a][j2*2], aV[a][j2*2+1]);
            *(__half2*)&vout[(size_t)i * SSQ + s0 + tx*4 + j2*2] = h;
        }
    }
}

// ---------------------------------------------------------------------------
// Q projection (fp32 out)
__global__ void proj_q_kernel(const float* __restrict__ proto,
                              const float* __restrict__ qw) {
    __shared__ float Ps[CCH][LLQ];
    __shared__ float Ws[CCH][17];
    int g = blockIdx.x >> 3, p = blockIdx.x & 7;
    int tid = threadIdx.x;
    const float* pg  = proto + (size_t)(g*PP + p) * CCH * LLQ;
    const float* qwg = qw + (size_t)g * CCH * CCH;

    for (int r = 0; r < 32; r++) {
        int id = tid + 256 * r;
        Ps[id >> 6][id & 63] = pg[id];
    }
    __syncthreads();

    int l = tid & 63;
    int ibase = tid >> 6;
    float acc[32];
    #pragma unroll
    for (int r = 0; r < 32; r++) acc[r] = 0.f;

    for (int c0 = 0; c0 < CCH; c0 += 16) {
        #pragma unroll
        for (int r = 0; r < 8; r++) {
            int id = tid + 256 * r;
            Ws[id >> 4][id & 15] = qwg[(id >> 4) * CCH + c0 + (id & 15)];
        }
        __syncthreads();
        float pc[16];
        #pragma unroll
        for (int cc = 0; cc < 16; cc++) pc[cc] = Ps[c0 + cc][l];
        #pragma unroll
        for (int r = 0; r < 32; r++) {
            int i = ibase + 4 * r;
            float a = acc[r];
            #pragma unroll
            for (int cc = 0; cc < 16; cc++) a += Ws[i][cc] * pc[cc];
            acc[r] = a;
        }
        __syncthreads();
    }
    float* qo = g_q + (size_t)(g*PP + p) * LLQ * CCH;
    #pragma unroll
    for (int r = 0; r < 32; r++) qo[l * CCH + ibase + 4*r] = acc[r];
}

// ---------------------------------------------------------------------------
// Attention v3 fixed. One CTA per (g,b,h,p,lc), 32 L-rows, 8 warps.
//
// smem (bytes):
//   KV double buf @0      : K tiles [2][128][40]h (10240B each) / V tiles [2][32][136]h (8704B each)
//   q_sh [32][40]h @20480 : 2560
//   q_sf [32][32]f @23040 : 4096
//   E [32][1032]h  @27136 : 66048
//   zsh[32]f @93184, iz[32]f @93312, red[8]f @93440
#define SMB_KV   0
#define KBUF_H   5120     // K buffer stride in HALF units (128*40)
#define VBUF_H   4352     // V buffer stride in HALF units (32*136)
#define SMB_QH   20480
#define SMB_QF   23040
#define SMB_E    27136
#define SMB_ZS   93184
#define SMB_IZ   93312
#define SMB_RED  93440
#define SMB_TOT  93504
#define EST      1032     // E stride in halfs
#define KST      40       // K tile stride in halfs
#define VST      136      // V tile stride in halfs

__device__ __forceinline__ void mma16816(float& c0, float& c1, float& c2, float& c3,
                                         uint32_t a0, uint32_t a1, uint32_t a2, uint32_t a3,
                                         uint32_t b0, uint32_t b1) {
    asm volatile("mma.sync.aligned.m16n8k16.row.col.f32.f16.f16.f32 "
                 "{%0,%1,%2,%3},{%4,%5,%6,%7},{%8,%9},{%0,%1,%2,%3};"
                 : "+f"(c0), "+f"(c1), "+f"(c2), "+f"(c3)
                 : "r"(a0), "r"(a1), "r"(a2), "r"(a3), "r"(b0), "r"(b1));
}
__device__ __forceinline__ uint32_t ldh2(const __half* p) {
    return *reinterpret_cast<const uint32_t*>(p);
}

__global__ void __launch_bounds__(256, 2) attn_kernel() {
    extern __shared__ char smraw[];
    __half* KVh  = (__half*)(smraw + SMB_KV);
    __half* q_sh = (__half*)(smraw + SMB_QH);
    float*  q_sf = (float*)(smraw + SMB_QF);
    __half* E    = (__half*)(smraw + SMB_E);
    float*  zsh  = (float*)(smraw + SMB_ZS);
    float*  iz   = (float*)(smraw + SMB_IZ);
    float*  red  = (float*)(smraw + SMB_RED);

    int idx = blockIdx.x;                  // 1536 = g(3) b(8) h(4) p(8) lc(2)
    int lc = idx & 1, p = (idx >> 1) & 7, h = (idx >> 4) & 3,
        b = (idx >> 6) & 7, g = idx >> 9;
    int tid = threadIdx.x, lane = tid & 31, w = tid >> 5;
    int gr = lane >> 2, tc = lane & 3;
    int lbase = lc * 32;

    const __half* Kg = g_kh + (size_t)(g*BB + b) * SSQ * CCH + h * DH;   // [s][128]+off
    const __half* Vg = g_vh + ((size_t)((g*BB + b) * CCH) + h * DH) * SSQ;
    const float*  Qg = g_q  + (size_t)(g*PP + p) * LLQ * CCH;

    // ---- q load (fp16 for mma, fp32 for dist) + zsh init ----
    #pragma unroll
    for (int r = 0; r < 4; r++) {
        int id = tid + 256 * r;            // 0..1023
        int row = id >> 5, d = id & 31;
        float f = Qg[(lbase + row) * CCH + h * DH + d];
        q_sf[row * 32 + d] = f;
        q_sh[row * KST + d] = __float2half(f);
    }
    if (tid < 32) zsh[tid] = 0.f;
    __syncthreads();                       // q_sh visible before fragment loads

    // K tile fill helper (st -> buffer bf); strides in HALF units
    auto loadK = [&](int st, int bf) {
        const __half* src = Kg + (size_t)st * 128 * CCH;
        __half* dst = KVh + bf * KBUF_H;
        #pragma unroll
        for (int it = 0; it < 2; it++) {
            int id = tid + 256 * it;       // 0..511
            int r = id >> 2, ch = id & 3;
            uint4 v = *(const uint4*)(src + (size_t)r * CCH + ch * 8);
            *(uint4*)(dst + r * KST + ch * 8) = v;
        }
    };
    auto loadV = [&](int st, int bf) {
        const __half* src = Vg + st * 128;
        __half* dst = KVh + bf * VBUF_H;
        #pragma unroll
        for (int it = 0; it < 2; it++) {
            int id = tid + 256 * it;       // 0..511
            int d = id >> 4, ch = id & 15;
            uint4 v = *(const uint4*)(src + (size_t)d * SSQ + ch * 8);
            *(uint4*)(dst + d * VST + ch * 8) = v;
        }
    };

    // ================= QK phase =================
    int mh = w >> 2;                       // 0/1 : rows mh*16..+16
    int ng = w & 3;                        // n block of 32 within 128-col tile
    int r_lo = mh * 16 + gr, r_hi = r_lo + 8;

    // A fragments (constant across st): 2 k-steps x 4 regs
    uint32_t aq[2][4];
    {
        const __half* qb = q_sh + r_lo * KST;
        #pragma unroll
        for (int ks = 0; ks < 2; ks++) {
            aq[ks][0] = ldh2(qb + ks*16 + tc*2);
            aq[ks][1] = ldh2(qb + 8*KST + ks*16 + tc*2);
            aq[ks][2] = ldh2(qb + ks*16 + tc*2 + 8);
            aq[ks][3] = ldh2(qb + 8*KST + ks*16 + tc*2 + 8);
        }
    }

    loadK(0, 0);
    float zlo = 0.f, zhi = 0.f;

    for (int st = 0; st < 8; st++) {
        __syncthreads();
        if (st + 1 < 8) loadK(st + 1, (st + 1) & 1);
        const __half* Kt = KVh + (st & 1) * KBUF_H;

        #pragma unroll
        for (int nt = 0; nt < 4; nt++) {
            float c0 = 0.f, c1 = 0.f, c2 = 0.f, c3 = 0.f;
            const __half* kb = Kt + (ng*32 + nt*8 + gr) * KST;
            #pragma unroll
            for (int ks = 0; ks < 2; ks++) {
                uint32_t b0 = ldh2(kb + ks*16 + tc*2);
                uint32_t b1 = ldh2(kb + ks*16 + tc*2 + 8);
                mma16816(c0, c1, c2, c3,
                         aq[ks][0], aq[ks][1], aq[ks][2], aq[ks][3], b0, b1);
            }
            float e0 = __expf(c0 * SCALE_F);
            float e1 = __expf(c1 * SCALE_F);
            float e2 = __expf(c2 * SCALE_F);
            float e3 = __expf(c3 * SCALE_F);
            zlo += e0 + e1; zhi += e2 + e3;
            int scol = st*128 + ng*32 + nt*8 + tc*2;
            *(__half2*)&E[r_lo * EST + scol] = __floats2half2_rn(e0, e1);
            *(__half2*)&E[r_hi * EST + scol] = __floats2half2_rn(e2, e3);
        }
    }
    // z reduce within 4-lane groups, atomics into zsh
    #pragma unroll
    for (int o = 1; o <= 2; o <<= 1) {
        zlo += __shfl_xor_sync(0xffffffffu, zlo, o);
        zhi += __shfl_xor_sync(0xffffffffu, zhi, o);
    }
    if (tc == 0) {
        atomicAdd(&zsh[r_lo], zlo);
        atomicAdd(&zsh[r_hi], zhi);
    }
    __syncthreads();                       // QK smem reads done; zsh complete
    if (tid < 32) iz[tid] = 1.f / zsh[tid];

    loadV(0, 0);                           // overlap V(0) fill with heat pass
    __syncthreads();                       // iz + E + V(0) visible

    // ================= heat =================
    float* hout = g_heat + (size_t)((g*BB + b) * PP + p) * SSQ;
    #pragma unroll
    for (int j = 0; j < 2; j++) {
        int wcol = tid + 256 * j;          // 0..511 half2 columns
        int scol = wcol * 2;
        float hs0 = 0.f, hs1 = 0.f;
        #pragma unroll
        for (int r = 0; r < 32; r++) {
            __half2 hv = *(__half2*)&E[r * EST + scol];
            float2 f2 = __half22float2(hv);
            float izr = iz[r];
            hs0 += f2.x * izr; hs1 += f2.y * izr;
        }
        atomicAdd(&hout[scol], hs0);
        atomicAdd(&hout[scol + 1], hs1);
    }

    // ================= PV phase =================
    int ndt = w & 3;                       // d block of 8 (mh reused for rows)
    float c0 = 0.f, c1 = 0.f, c2 = 0.f, c3 = 0.f;
    const __half* ElA = E + r_lo * EST;
    const __half* ElB = E + r_hi * EST;

    for (int st = 0; st < 8; st++) {
        __syncthreads();
        if (st + 1 < 8) loadV(st + 1, (st + 1) & 1);
        const __half* Vt = KVh + (st & 1) * VBUF_H;
        const __half* vb = Vt + (ndt*8 + gr) * VST;

        #pragma unroll
        for (int ks = 0; ks < 8; ks++) {
            int kl = ks * 16;
            int sg = st * 128 + kl;
            uint32_t a0 = ldh2(ElA + sg + tc*2);
            uint32_t a1 = ldh2(ElB + sg + tc*2);
            uint32_t a2 = ldh2(ElA + sg + tc*2 + 8);
            uint32_t a3 = ldh2(ElB + sg + tc*2 + 8);
            uint32_t b0 = ldh2(vb + kl + tc*2);
            uint32_t b1 = ldh2(vb + kl + tc*2 + 8);
            mma16816(c0, c1, c2, c3, a0, a1, a2, a3, b0, b1);
        }
    }

    // normalize + dist
    float izA = iz[r_lo], izB = iz[r_hi];
    int d0 = ndt*8 + tc*2, d1 = d0 + 1;
    float o00 = c0 * izA, o01 = c1 * izA, o10 = c2 * izB, o11 = c3 * izB;
    float dist_acc;
    {
        float e;
        e = q_sf[r_lo * 32 + d0] - o00; dist_acc  = e * e;
        e = q_sf[r_lo * 32 + d1] - o01; dist_acc += e * e;
        e = q_sf[r_hi * 32 + d0] - o10; dist_acc += e * e;
        e = q_sf[r_hi * 32 + d1] - o11; dist_acc += e * e;
    }
    #pragma unroll
    for (int o = 16; o; o >>= 1) dist_acc += __shfl_xor_sync(0xffffffffu, dist_acc, o);
    if (lane == 0) red[w] = dist_acc;
    __syncthreads();
    if (w == 0) {
        float v = (lane < 8) ? red[lane] : 0.f;
        #pragma unroll
        for (int o = 4; o; o >>= 1) v += __shfl_xor_sync(0xffffffffu, v, o);
        if (lane == 0) atomicAdd(&g_dist[(g*BB + b) * PP + p], v);
    }
}

// ---------------------------------------------------------------------------
// Finalize: dist/(64*128) and argmax(heat) -> out = [dist(8x24) | idx(8x24)]
__global__ void finalize_kernel(float* __restrict__ out, int out_size) {
    __shared__ float bv[128];
    __shared__ int  bidx[128];
    int gbp = blockIdx.x;
    int tid = threadIdx.x;
    const float* hrow = g_heat + (size_t)gbp * SSQ;
    float best = -1e30f; int bi = 0;
    for (int j = tid; j < SSQ; j += 128) {
        float v = hrow[j];
        if (v > best) { best = v; bi = j; }
    }
    bv[tid] = best; bidx[tid] = bi;
    __syncthreads();
    for (int s = 64; s; s >>= 1) {
        if (tid < s) {
            if (bv[tid + s] > bv[tid] ||
                (bv[tid + s] == bv[tid] && bidx[tid + s] < bidx[tid])) {
                bv[tid] = bv[tid + s]; bidx[tid] = bidx[tid + s];
            }
        }
        __syncthreads();
    }
    if (tid == 0) {
        int g = gbp >> 6, b = (gbp >> 3) & 7, p = gbp & 7;
        int col = g * PP + p;
        out[b * 24 + col] = g_dist[gbp] * (1.f / (64.f * 128.f));
        if (out_size >= 384)
            out[192 + b * 24 + col] = (float)bidx[0];
    }
}

// ---------------------------------------------------------------------------
extern "C" void kernel_launch(void* const* d_in, const int* in_sizes, int n_in,
                              void* d_out, int out_size) {
    const float* x     = (const float*)d_in[0];
    const float* proto = (const float*)d_in[1];
    const float* qw    = (const float*)d_in[2];
    const float* kw    = (const float*)d_in[3];
    const float* vw    = (const float*)d_in[4];
    float* out = (float*)d_out;

    cudaFuncSetAttribute(attn_kernel,
                         cudaFuncAttributeMaxDynamicSharedMemorySize, SMB_TOT);

    zero_kernel<<<768, 256>>>();
    proj_kv_kernel<<<dim3(16, 2, 24), 256>>>(x, kw, vw);
    proj_q_kernel<<<24, 256>>>(proto, qw);
    attn_kernel<<<1536, 256, SMB_TOT>>>();
    finalize_kernel<<<192, 128>>>(out, out_size);
}

// round 7
// speedup vs baseline: 3.5632x; 1.3343x over previous
#include <cuda_runtime.h>
#include <cuda_fp16.h>
#include <cstdint>

#define NG 3
#define PP 8
#define BB 8
#define CCH 128
#define SSQ 1024
#define LLQ 64
#define HH 4
#define DH 32
#define SCALE_F 0.17677669529663687f

// Scratch (static __device__ arrays: allocation-free per harness rules)
__device__ __align__(256) __half g_xh [BB*SSQ*CCH];     // [b][s][c]  fp16
__device__ __align__(256) __half g_wkh[NG*CCH*CCH];     // [g][i][c]  fp16
__device__ __align__(256) __half g_wvh[NG*CCH*CCH];     // [g][i][c]  fp16
__device__ __align__(256) __half g_kh[NG*BB*SSQ*CCH];   // [g][b][s][c]  fp16
__device__ __align__(256) __half g_vh[NG*BB*CCH*SSQ];   // [g][b][c][s]  fp16
__device__ __align__(256) float  g_q [NG*PP*LLQ*CCH];   // [g][p][l][i]  fp32
__device__ __align__(256) float  g_heat[NG*BB*PP*SSQ];  // [g][b][p][s]
__device__ float g_dist[NG*BB*PP];                      // [g][b][p]

__device__ __forceinline__ void mma16816(float& c0, float& c1, float& c2, float& c3,
                                         uint32_t a0, uint32_t a1, uint32_t a2, uint32_t a3,
                                         uint32_t b0, uint32_t b1) {
    asm volatile("mma.sync.aligned.m16n8k16.row.col.f32.f16.f16.f32 "
                 "{%0,%1,%2,%3},{%4,%5,%6,%7},{%8,%9},{%0,%1,%2,%3};"
                 : "+f"(c0), "+f"(c1), "+f"(c2), "+f"(c3)
                 : "r"(a0), "r"(a1), "r"(a2), "r"(a3), "r"(b0), "r"(b1));
}
__device__ __forceinline__ uint32_t ldh2(const __half* p) {
    return *reinterpret_cast<const uint32_t*>(p);
}
__device__ __forceinline__ uint32_t packh2(float a, float b) {
    __half2 h = __floats2half2_rn(a, b);
    return reinterpret_cast<uint32_t&>(h);
}

// ---------------------------------------------------------------------------
__global__ void zero_kernel() {
    int i = blockIdx.x * 256 + threadIdx.x;
    if (i < NG*BB*PP*SSQ) g_heat[i] = 0.f;
    if (i < NG*BB*PP)     g_dist[i] = 0.f;
}

// ---------------------------------------------------------------------------
// x [b][c][s] fp32 -> g_xh [b][s][c] fp16 (transpose 64x64 tiles)
__global__ void convert_x_kernel(const float* __restrict__ x) {
    __shared__ float Ts[64][68];
    int b = blockIdx.z, c0 = blockIdx.y * 64, s0 = blockIdx.x * 64;
    int tid = threadIdx.x;
    const float* xb = x + ((size_t)b * CCH + c0) * SSQ + s0;
    #pragma unroll
    for (int r = 0; r < 4; r++) {
        int id = tid + 256 * r;              // 0..1023 float4 units
        int cc = id >> 4, f4 = id & 15;
        float4 v = *(const float4*)(xb + (size_t)cc * SSQ + f4 * 4);
        *(float4*)&Ts[cc][f4 * 4] = v;
    }
    __syncthreads();
    __half* xo = g_xh + ((size_t)b * SSQ + s0) * CCH + c0;
    #pragma unroll
    for (int r = 0; r < 8; r++) {
        int id = tid + 256 * r;              // 0..2047 half2 units
        int ss = id >> 5, cp = id & 31;
        __half2 h = __floats2half2_rn(Ts[cp*2][ss], Ts[cp*2+1][ss]);
        *(__half2*)(xo + (size_t)ss * CCH + cp * 2) = h;
    }
}

// ---------------------------------------------------------------------------
__global__ void convert_w_kernel(const float* __restrict__ kw,
                                 const float* __restrict__ vw) {
    int i = blockIdx.x * 256 + threadIdx.x;  // 49152 total
    g_wkh[i] = __float2half(kw[i]);
    g_wvh[i] = __float2half(vw[i]);
}

// ---------------------------------------------------------------------------
// K/V projection via fp16 mma: out K[s][i], V[i][s] per (g,b).
// grid (8 s-tiles of 128, 2 i-halves of 64, 24 g*b), 256 threads.
// smem: Xs [128 s][136]h @0, Wk [64][136]h @34816, Wv @52224, Stage @69632 (18432B)
#define PJ_XS   0
#define PJ_WK   34816
#define PJ_WV   52224
#define PJ_ST   69632
#define PJ_TOT  88064

__global__ void __launch_bounds__(256, 2) proj_kv_mma_kernel() {
    extern __shared__ char smraw[];
    __half* Xs = (__half*)(smraw + PJ_XS);   // [128][136]
    __half* Wk = (__half*)(smraw + PJ_WK);   // [64][136]
    __half* Wv = (__half*)(smraw + PJ_WV);   // [64][136]
    __half* St = (__half*)(smraw + PJ_ST);

    int s0 = blockIdx.x * 128, i1 = blockIdx.y * 64;
    int gb = blockIdx.z;
    int g = gb >> 3, b = gb & 7;
    int tid = threadIdx.x, lane = tid & 31, w = tid >> 5;
    int gr = lane >> 2, tc = lane & 3;
    int mt = w & 3, nh = w >> 2;

    // load tiles
    {
        const __half* src = g_xh + ((size_t)b * SSQ + s0) * CCH;
        #pragma unroll
        for (int r = 0; r < 8; r++) {
            int id = tid + 256 * r;          // 0..2047
            int row = id >> 4, q = id & 15;
            *(uint4*)(Xs + row * 136 + q * 8) =
                *(const uint4*)(src + (size_t)row * CCH + q * 8);
        }
        const __half* sk = g_wkh + (size_t)(g * CCH + i1) * CCH;
        const __half* sv = g_wvh + (size_t)(g * CCH + i1) * CCH;
        #pragma unroll
        for (int r = 0; r < 4; r++) {
            int id = tid + 256 * r;          // 0..1023
            int row = id >> 4, q = id & 15;
            *(uint4*)(Wk + row * 136 + q * 8) = *(const uint4*)(sk + (size_t)row * CCH + q * 8);
            *(uint4*)(Wv + row * 136 + q * 8) = *(const uint4*)(sv + (size_t)row * CCH + q * 8);
        }
    }
    __syncthreads();

    // ---- K = Wk @ X^T ----
    float cK[8][4] = {};
    {
        const __half* A = Wk + (mt * 16) * 136;
        #pragma unroll
        for (int kk = 0; kk < 8; kk++) {
            uint32_t a0 = ldh2(A + gr * 136 + kk*16 + tc*2);
            uint32_t a1 = ldh2(A + (gr+8) * 136 + kk*16 + tc*2);
            uint32_t a2 = ldh2(A + gr * 136 + kk*16 + tc*2 + 8);
            uint32_t a3 = ldh2(A + (gr+8) * 136 + kk*16 + tc*2 + 8);
            #pragma unroll
            for (int nt = 0; nt < 8; nt++) {
                const __half* Bp = Xs + (nh*64 + nt*8 + gr) * 136 + kk*16 + tc*2;
                uint32_t b0 = ldh2(Bp), b1 = ldh2(Bp + 8);
                mma16816(cK[nt][0], cK[nt][1], cK[nt][2], cK[nt][3],
                         a0, a1, a2, a3, b0, b1);
            }
        }
    }
    // stage K as [s 128][72]h
    #pragma unroll
    for (int nt = 0; nt < 8; nt++) {
        int sl = nh*64 + nt*8 + tc*2;
        int il = mt*16 + gr;
        St[sl * 72 + il]       = __float2half(cK[nt][0]);
        St[(sl+1) * 72 + il]   = __float2half(cK[nt][1]);
        St[sl * 72 + il + 8]   = __float2half(cK[nt][2]);
        St[(sl+1) * 72 + il+8] = __float2half(cK[nt][3]);
    }
    __syncthreads();
    // write K [s][i]
    {
        __half* kout = g_kh + (size_t)gb * SSQ * CCH;
        #pragma unroll
        for (int r = 0; r < 4; r++) {
            int id = tid + 256 * r;          // 0..1023
            int row = id >> 3, q = id & 7;
            *(uint4*)(kout + (size_t)(s0 + row) * CCH + i1 + q * 8) =
                *(const uint4*)(St + row * 72 + q * 8);
        }
    }

    // ---- V = Wv @ X^T ----
    float cV[8][4] = {};
    {
        const __half* A = Wv + (mt * 16) * 136;
        #pragma unroll
        for (int kk = 0; kk < 8; kk++) {
            uint32_t a0 = ldh2(A + gr * 136 + kk*16 + tc*2);
            uint32_t a1 = ldh2(A + (gr+8) * 136 + kk*16 + tc*2);
            uint32_t a2 = ldh2(A + gr * 136 + kk*16 + tc*2 + 8);
            uint32_t a3 = ldh2(A + (gr+8) * 136 + kk*16 + tc*2 + 8);
            #pragma unroll
            for (int nt = 0; nt < 8; nt++) {
                const __half* Bp = Xs + (nh*64 + nt*8 + gr) * 136 + kk*16 + tc*2;
                uint32_t b0 = ldh2(Bp), b1 = ldh2(Bp + 8);
                mma16816(cV[nt][0], cV[nt][1], cV[nt][2], cV[nt][3],
                         a0, a1, a2, a3, b0, b1);
            }
        }
    }
    __syncthreads();                         // K write-out reads of St done
    // stage V as [i 64][136]h
    #pragma unroll
    for (int nt = 0; nt < 8; nt++) {
        int sl = nh*64 + nt*8 + tc*2;
        int il = mt*16 + gr;
        *(__half2*)(St + il * 136 + sl)       = __floats2half2_rn(cV[nt][0], cV[nt][1]);
        *(__half2*)(St + (il+8) * 136 + sl)   = __floats2half2_rn(cV[nt][2], cV[nt][3]);
    }
    __syncthreads();
    // write V [i][s]
    {
        __half* vout = g_vh + (size_t)gb * CCH * SSQ;
        #pragma unroll
        for (int r = 0; r < 4; r++) {
            int id = tid + 256 * r;          // 0..1023
            int row = id >> 4, q = id & 15;
            *(uint4*)(vout + (size_t)(i1 + row) * SSQ + s0 + q * 8) =
                *(const uint4*)(St + row * 136 + q * 8);
        }
    }
}

// ---------------------------------------------------------------------------
// Q projection (fp32, unchanged)
__global__ void proj_q_kernel(const float* __restrict__ proto,
                              const float* __restrict__ qw) {
    __shared__ float Ps[CCH][LLQ];
    __shared__ float Ws[CCH][17];
    int g = blockIdx.x >> 3, p = blockIdx.x & 7;
    int tid = threadIdx.x;
    const float* pg  = proto + (size_t)(g*PP + p) * CCH * LLQ;
    const float* qwg = qw + (size_t)g * CCH * CCH;

    for (int r = 0; r < 32; r++) {
        int id = tid + 256 * r;
        Ps[id >> 6][id & 63] = pg[id];
    }
    __syncthreads();

    int l = tid & 63;
    int ibase = tid >> 6;
    float acc[32];
    #pragma unroll
    for (int r = 0; r < 32; r++) acc[r] = 0.f;

    for (int c0 = 0; c0 < CCH; c0 += 16) {
        #pragma unroll
        for (int r = 0; r < 8; r++) {
            int id = tid + 256 * r;
            Ws[id >> 4][id & 15] = qwg[(id >> 4) * CCH + c0 + (id & 15)];
        }
        __syncthreads();
        float pc[16];
        #pragma unroll
        for (int cc = 0; cc < 16; cc++) pc[cc] = Ps[c0 + cc][l];
        #pragma unroll
        for (int r = 0; r < 32; r++) {
            int i = ibase + 4 * r;
            float a = acc[r];
            #pragma unroll
            for (int cc = 0; cc < 16; cc++) a += Ws[i][cc] * pc[cc];
            acc[r] = a;
        }
        __syncthreads();
    }
    float* qo = g_q + (size_t)(g*PP + p) * LLQ * CCH;
    #pragma unroll
    for (int r = 0; r < 32; r++) qo[l * CCH + ibase + 4*r] = acc[r];
}

// ---------------------------------------------------------------------------
// Fused flash attention. One CTA per (g,b,h,p,lc), 32 L-rows, 8 warps.
// QK mma -> exp -> register half2 fragments feed PV mma directly.
// E stored once (heat only). PV partials reduced across ng-warps via smem atomics.
//
// smem (bytes):
//   K dbuf  @0      : 2 x [128][40]h  = 20480
//   V dbuf  @20480  : 2 x [32][136]h  = 17408
//   E       @37888  : [32][1032]h     = 66048
//   out_sf  @103936 : [32][33]f       = 4224
//   zsh @108160 (128), iz @108288 (128), red @108416 (32)
#define AT_K     0
#define AT_V     20480
#define AT_E     37888
#define AT_OUT   103936
#define AT_ZS    108160
#define AT_IZ    108288
#define AT_RED   108416
#define AT_TOT   108448
#define KBUF_H   5120     // K buffer stride (halfs) = 128*40
#define VBUF_H   4352     // V buffer stride (halfs) = 32*136
#define EST      1032
#define KST      40
#define VST      136

__global__ void __launch_bounds__(256, 2) attn_kernel() {
    extern __shared__ char smraw[];
    __half* Kb   = (__half*)(smraw + AT_K);
    __half* Vb   = (__half*)(smraw + AT_V);
    __half* E    = (__half*)(smraw + AT_E);
    float* out_sf= (float*)(smraw + AT_OUT);   // [32][33]
    float* zsh   = (float*)(smraw + AT_ZS);
    float* iz    = (float*)(smraw + AT_IZ);
    float* red   = (float*)(smraw + AT_RED);

    int idx = blockIdx.x;                  // 1536 = g(3) b(8) h(4) p(8) lc(2)
    int lc = idx & 1, p = (idx >> 1) & 7, h = (idx >> 4) & 3,
        b = (idx >> 6) & 7, g = idx >> 9;
    int tid = threadIdx.x, lane = tid & 31, w = tid >> 5;
    int gr = lane >> 2, tc = lane & 3;
    int lbase = lc * 32;

    const __half* Kg = g_kh + (size_t)(g*BB + b) * SSQ * CCH + h * DH;   // [s][128]+off
    const __half* Vg = g_vh + ((size_t)((g*BB + b) * CCH) + h * DH) * SSQ;
    const float*  Qg = g_q  + (size_t)(g*PP + p) * LLQ * CCH;

    // zero reduction buffers
    #pragma unroll
    for (int r = 0; r < 5; r++) {
        int id = tid + 256 * r;
        if (id < 1056) out_sf[id] = 0.f;
    }
    if (tid < 32) zsh[tid] = 0.f;

    int mh = w >> 2;                       // row half: rows mh*16..+16
    int ng = w & 3;                        // s-block of 32 within 128-s tile
    int r_lo = mh * 16 + gr, r_hi = r_lo + 8;

    // A fragments for QK from global q (fp32 -> half2)
    uint32_t aq[2][4];
    {
        const float* q0 = Qg + (size_t)(lbase + r_lo) * CCH + h * DH;
        const float* q1 = q0 + 8 * CCH;
        #pragma unroll
        for (int ks = 0; ks < 2; ks++) {
            float2 f0 = *(const float2*)(q0 + ks*16 + tc*2);
            float2 f1 = *(const float2*)(q1 + ks*16 + tc*2);
            float2 f2 = *(const float2*)(q0 + ks*16 + tc*2 + 8);
            float2 f3 = *(const float2*)(q1 + ks*16 + tc*2 + 8);
            aq[ks][0] = packh2(f0.x, f0.y);
            aq[ks][1] = packh2(f1.x, f1.y);
            aq[ks][2] = packh2(f2.x, f2.y);
            aq[ks][3] = packh2(f3.x, f3.y);
        }
    }

    auto loadK = [&](int st, int bf) {
        const __half* src = Kg + (size_t)st * 128 * CCH;
        __half* dst = Kb + bf * KBUF_H;
        #pragma unroll
        for (int it = 0; it < 2; it++) {
            int id = tid + 256 * it;       // 0..511
            int r = id >> 2, ch = id & 3;
            *(uint4*)(dst + r * KST + ch * 8) =
                *(const uint4*)(src + (size_t)r * CCH + ch * 8);
        }
    };
    auto loadV = [&](int st, int bf) {
        const __half* src = Vg + st * 128;
        __half* dst = Vb + bf * VBUF_H;
        #pragma unroll
        for (int it = 0; it < 2; it++) {
            int id = tid + 256 * it;       // 0..511
            int d = id >> 4, ch = id & 15;
            *(uint4*)(dst + d * VST + ch * 8) =
                *(const uint4*)(src + (size_t)d * SSQ + ch * 8);
        }
    };

    loadK(0, 0);
    loadV(0, 0);

    float zlo = 0.f, zhi = 0.f;
    float pv[4][4] = {};                   // out C tiles: nd=0..3, warp's s-slice partial

    for (int st = 0; st < 8; st++) {
        __syncthreads();
        if (st < 7) { loadK(st + 1, (st + 1) & 1); loadV(st + 1, (st + 1) & 1); }
        const __half* Kt = Kb + (st & 1) * KBUF_H;
        const __half* Vt = Vb + (st & 1) * VBUF_H;

        #pragma unroll
        for (int j = 0; j < 2; j++) {      // two 16-s k-blocks within warp's 32 s
            uint32_t a0, a1, a2, a3;       // PV A fragments built from exp(QK)
            // ---- nt = 2j ----
            {
                float c0 = 0.f, c1 = 0.f, c2 = 0.f, c3 = 0.f;
                const __half* kb = Kt + (ng*32 + (2*j)*8 + gr) * KST;
                #pragma unroll
                for (int ks = 0; ks < 2; ks++) {
                    uint32_t b0 = ldh2(kb + ks*16 + tc*2);
                    uint32_t b1 = ldh2(kb + ks*16 + tc*2 + 8);
                    mma16816(c0, c1, c2, c3,
                             aq[ks][0], aq[ks][1], aq[ks][2], aq[ks][3], b0, b1);
                }
                float e0 = __expf(c0 * SCALE_F), e1 = __expf(c1 * SCALE_F);
                float e2 = __expf(c2 * SCALE_F), e3 = __expf(c3 * SCALE_F);
                zlo += e0 + e1; zhi += e2 + e3;
                a0 = packh2(e0, e1); a1 = packh2(e2, e3);
                int scol = st*128 + ng*32 + (2*j)*8 + tc*2;
                *(uint32_t*)&E[r_lo * EST + scol] = a0;
                *(uint32_t*)&E[r_hi * EST + scol] = a1;
            }
            // ---- nt = 2j+1 ----
            {
                float c0 = 0.f, c1 = 0.f, c2 = 0.f, c3 = 0.f;
                const __half* kb = Kt + (ng*32 + (2*j+1)*8 + gr) * KST;
                #pragma unroll
                for (int ks = 0; ks < 2; ks++) {
                    uint32_t b0 = ldh2(kb + ks*16 + tc*2);
                    uint32_t b1 = ldh2(kb + ks*16 + tc*2 + 8);
                    mma16816(c0, c1, c2, c3,
                             aq[ks][0], aq[ks][1], aq[ks][2], aq[ks][3], b0, b1);
                }
                float e0 = __expf(c0 * SCALE_F), e1 = __expf(c1 * SCALE_F);
                float e2 = __expf(c2 * SCALE_F), e3 = __expf(c3 * SCALE_F);
                zlo += e0 + e1; zhi += e2 + e3;
                a2 = packh2(e0, e1); a3 = packh2(e2, e3);
                int scol = st*128 + ng*32 + (2*j+1)*8 + tc*2;
                *(uint32_t*)&E[r_lo * EST + scol] = a2;
                *(uint32_t*)&E[r_hi * EST + scol] = a3;
            }
            // ---- PV: A = exp fragments, B = V[d][s] col-major over this k-block ----
            int sloc = ng*32 + j*16 + tc*2;
            #pragma unroll
            for (int nd = 0; nd < 4; nd++) {
                const __half* vbp = Vt + (nd*8 + gr) * VST + sloc;
                uint32_t b0 = ldh2(vbp);
                uint32_t b1 = ldh2(vbp + 8);
                mma16816(pv[nd][0], pv[nd][1], pv[nd][2], pv[nd][3],
                         a0, a1, a2, a3, b0, b1);
            }
        }
    }
    __syncthreads();                       // compute done, E complete

    // ---- Z reduction ----
    #pragma unroll
    for (int o = 1; o <= 2; o <<= 1) {
        zlo += __shfl_xor_sync(0xffffffffu, zlo, o);
        zhi += __shfl_xor_sync(0xffffffffu, zhi, o);
    }
    if (tc == 0) {
        atomicAdd(&zsh[r_lo], zlo);
        atomicAdd(&zsh[r_hi], zhi);
    }
    // ---- out partial reduction across ng-warps ----
    #pragma unroll
    for (int nd = 0; nd < 4; nd++) {
        int d = nd*8 + tc*2;
        atomicAdd(&out_sf[r_lo*33 + d],     pv[nd][0]);
        atomicAdd(&out_sf[r_lo*33 + d + 1], pv[nd][1]);
        atomicAdd(&out_sf[r_hi*33 + d],     pv[nd][2]);
        atomicAdd(&out_sf[r_hi*33 + d + 1], pv[nd][3]);
    }
    __syncthreads();
    if (tid < 32) iz[tid] = 1.f / zsh[tid];
    __syncthreads();

    // ---- heat ----
    float* hout = g_heat + (size_t)((g*BB + b) * PP + p) * SSQ;
    #pragma unroll
    for (int j = 0; j < 2; j++) {
        int scol = (tid + 256 * j) * 2;
        float hs0 = 0.f, hs1 = 0.f;
        #pragma unroll
        for (int r = 0; r < 32; r++) {
            __half2 hv = *(__half2*)&E[r * EST + scol];
            float2 f2 = __half22float2(hv);
            float izr = iz[r];
            hs0 += f2.x * izr; hs1 += f2.y * izr;
        }
        atomicAdd(&hout[scol], hs0);
        atomicAdd(&hout[scol + 1], hs1);
    }

    // ---- dist ----
    float dacc = 0.f;
    #pragma unroll
    for (int r = 0; r < 4; r++) {
        int id = tid + 256 * r;            // 0..1023
        int row = id >> 5, d = id & 31;
        float o = out_sf[row*33 + d] * iz[row];
        float qv = Qg[(size_t)(lbase + row) * CCH + h * DH + d];
        float e = qv - o;
        dacc += e * e;
    }
    #pragma unroll
    for (int o = 16; o; o >>= 1) dacc += __shfl_xor_sync(0xffffffffu, dacc, o);
    if (lane == 0) red[w] = dacc;
    __syncthreads();
    if (w == 0) {
        float v = (lane < 8) ? red[lane] : 0.f;
        #pragma unroll
        for (int o = 4; o; o >>= 1) v += __shfl_xor_sync(0xffffffffu, v, o);
        if (lane == 0) atomicAdd(&g_dist[(g*BB + b) * PP + p], v);
    }
}

// ---------------------------------------------------------------------------
// Finalize: dist/(64*128) and argmax(heat) -> out = [dist(8x24) | idx(8x24)]
__global__ void finalize_kernel(float* __restrict__ out, int out_size) {
    __shared__ float bv[128];
    __shared__ int  bidx[128];
    int gbp = blockIdx.x;
    int tid = threadIdx.x;
    const float* hrow = g_heat + (size_t)gbp * SSQ;
    float best = -1e30f; int bi = 0;
    for (int j = tid; j < SSQ; j += 128) {
        float v = hrow[j];
        if (v > best) { best = v; bi = j; }
    }
    bv[tid] = best; bidx[tid] = bi;
    __syncthreads();
    for (int s = 64; s; s >>= 1) {
        if (tid < s) {
            if (bv[tid + s] > bv[tid] ||
                (bv[tid + s] == bv[tid] && bidx[tid + s] < bidx[tid])) {
                bv[tid] = bv[tid + s]; bidx[tid] = bidx[tid + s];
            }
        }
        __syncthreads();
    }
    if (tid == 0) {
        int g = gbp >> 6, b = (gbp >> 3) & 7, p = gbp & 7;
        int col = g * PP + p;
        out[b * 24 + col] = g_dist[gbp] * (1.f / (64.f * 128.f));
        if (out_size >= 384)
            out[192 + b * 24 + col] = (float)bidx[0];
    }
}

// ---------------------------------------------------------------------------
extern "C" void kernel_launch(void* const* d_in, const int* in_sizes, int n_in,
                              void* d_out, int out_size) {
    const float* x     = (const float*)d_in[0];
    const float* proto = (const float*)d_in[1];
    const float* qw    = (const float*)d_in[2];
    const float* kw    = (const float*)d_in[3];
    const float* vw    = (const float*)d_in[4];
    float* out = (float*)d_out;

    cudaFuncSetAttribute(attn_kernel,
                         cudaFuncAttributeMaxDynamicSharedMemorySize, AT_TOT);
    cudaFuncSetAttribute(proj_kv_mma_kernel,
                         cudaFuncAttributeMaxDynamicSharedMemorySize, PJ_TOT);

    zero_kernel<<<768, 256>>>();
    convert_x_kernel<<<dim3(16, 2, 8), 256>>>(x);
    convert_w_kernel<<<192, 256>>>(kw, vw);
    proj_kv_mma_kernel<<<dim3(8, 2, 24), 256, PJ_TOT>>>();
    proj_q_kernel<<<24, 256>>>(proto, qw);
    attn_kernel<<<1536, 256, AT_TOT>>>();
    finalize_kernel<<<192, 128>>>(out, out_size);
}

// round 9
// speedup vs baseline: 3.8982x; 1.0940x over previous
#include <cuda_runtime.h>
#include <cuda_fp16.h>
#include <cstdint>

#define NG 3
#define PP 8
#define BB 8
#define CCH 128
#define SSQ 1024
#define LLQ 64
#define HH 4
#define DH 32
#define SCALE_F 0.17677669529663687f

// Scratch (static __device__ arrays: allocation-free per harness rules)
__device__ __align__(256) __half g_xh [BB*SSQ*CCH];     // [b][s][c]  fp16
__device__ __align__(256) __half g_wkh[NG*CCH*CCH];     // [g][i][c]  fp16
__device__ __align__(256) __half g_wvh[NG*CCH*CCH];     // [g][i][c]  fp16
__device__ __align__(256) __half g_kh[NG*BB*SSQ*CCH];   // [g][b][s][c]  fp16
__device__ __align__(256) __half g_vh[NG*BB*CCH*SSQ];   // [g][b][c][s]  fp16
__device__ __align__(256) float  g_q [NG*PP*LLQ*CCH];   // [g][p][l][i]  fp32
__device__ __align__(256) float  g_heat[NG*BB*PP*SSQ];  // [g][b][p][s]
__device__ float g_dist[NG*BB*PP];                      // [g][b][p]

__device__ __forceinline__ void mma16816(float& c0, float& c1, float& c2, float& c3,
                                         uint32_t a0, uint32_t a1, uint32_t a2, uint32_t a3,
                                         uint32_t b0, uint32_t b1) {
    asm volatile("mma.sync.aligned.m16n8k16.row.col.f32.f16.f16.f32 "
                 "{%0,%1,%2,%3},{%4,%5,%6,%7},{%8,%9},{%0,%1,%2,%3};"
                 : "+f"(c0), "+f"(c1), "+f"(c2), "+f"(c3)
                 : "r"(a0), "r"(a1), "r"(a2), "r"(a3), "r"(b0), "r"(b1));
}
__device__ __forceinline__ uint32_t ldh2(const __half* p) {
    return *reinterpret_cast<const uint32_t*>(p);
}
__device__ __forceinline__ uint32_t packh2(float a, float b) {
    __half2 h = __floats2half2_rn(a, b);
    return reinterpret_cast<uint32_t&>(h);
}

// ---------------------------------------------------------------------------
// prep: zero heat/dist + convert weights to fp16. grid 768 x 256.
__global__ void prep_kernel(const float* __restrict__ kw,
                            const float* __restrict__ vw) {
    int i = blockIdx.x * 256 + threadIdx.x;     // 0..196607
    g_heat[i] = 0.f;                             // exactly NG*BB*PP*SSQ
    if (i < NG*BB*PP) g_dist[i] = 0.f;
    if (i < NG*CCH*CCH) {
        g_wkh[i] = __float2half(kw[i]);
        g_wvh[i] = __float2half(vw[i]);
    }
}

// ---------------------------------------------------------------------------
// x [b][c][s] fp32 -> g_xh [b][s][c] fp16 (transpose 64x64 tiles)
__global__ void convert_x_kernel(const float* __restrict__ x) {
    __shared__ float Ts[64][68];
    int b = blockIdx.z, c0 = blockIdx.y * 64, s0 = blockIdx.x * 64;
    int tid = threadIdx.x;
    const float* xb = x + ((size_t)b * CCH + c0) * SSQ + s0;
    #pragma unroll
    for (int r = 0; r < 4; r++) {
        int id = tid + 256 * r;              // 0..1023 float4 units
        int cc = id >> 4, f4 = id & 15;
        float4 v = *(const float4*)(xb + (size_t)cc * SSQ + f4 * 4);
        *(float4*)&Ts[cc][f4 * 4] = v;
    }
    __syncthreads();
    __half* xo = g_xh + ((size_t)b * SSQ + s0) * CCH + c0;
    #pragma unroll
    for (int r = 0; r < 8; r++) {
        int id = tid + 256 * r;              // 0..2047 half2 units
        int ss = id >> 5, cp = id & 31;
        __half2 h = __floats2half2_rn(Ts[cp*2][ss], Ts[cp*2+1][ss]);
        *(__half2*)(xo + (size_t)ss * CCH + cp * 2) = h;
    }
}

// ---------------------------------------------------------------------------
// K/V projection via fp16 mma: out K[s][i], V[i][s] per (g,b).
// grid (8 s-tiles of 128, 2 i-halves of 64, 24 g*b), 256 threads.
#define PJ_XS   0
#define PJ_WK   34816
#define PJ_WV   52224
#define PJ_ST   69632
#define PJ_TOT  88064

__global__ void __launch_bounds__(256, 2) proj_kv_mma_kernel() {
    extern __shared__ char smraw[];
    __half* Xs = (__half*)(smraw + PJ_XS);   // [128][136]
    __half* Wk = (__half*)(smraw + PJ_WK);   // [64][136]
    __half* Wv = (__half*)(smraw + PJ_WV);   // [64][136]
    __half* St = (__half*)(smraw + PJ_ST);

    int s0 = blockIdx.x * 128, i1 = blockIdx.y * 64;
    int gb = blockIdx.z;
    int g = gb >> 3, b = gb & 7;
    int tid = threadIdx.x, lane = tid & 31, w = tid >> 5;
    int gr = lane >> 2, tc = lane & 3;
    int mt = w & 3, nh = w >> 2;

    {
        const __half* src = g_xh + ((size_t)b * SSQ + s0) * CCH;
        #pragma unroll
        for (int r = 0; r < 8; r++) {
            int id = tid + 256 * r;          // 0..2047
            int row = id >> 4, q = id & 15;
            *(uint4*)(Xs + row * 136 + q * 8) =
                *(const uint4*)(src + (size_t)row * CCH + q * 8);
        }
        const __half* sk = g_wkh + (size_t)(g * CCH + i1) * CCH;
        const __half* sv = g_wvh + (size_t)(g * CCH + i1) * CCH;
        #pragma unroll
        for (int r = 0; r < 4; r++) {
            int id = tid + 256 * r;          // 0..1023
            int row = id >> 4, q = id & 15;
            *(uint4*)(Wk + row * 136 + q * 8) = *(const uint4*)(sk + (size_t)row * CCH + q * 8);
            *(uint4*)(Wv + row * 136 + q * 8) = *(const uint4*)(sv + (size_t)row * CCH + q * 8);
        }
    }
    __syncthreads();

    // ---- K = Wk @ X^T ----
    float cK[8][4] = {};
    {
        const __half* A = Wk + (mt * 16) * 136;
        #pragma unroll
        for (int kk = 0; kk < 8; kk++) {
            uint32_t a0 = ldh2(A + gr * 136 + kk*16 + tc*2);
            uint32_t a1 = ldh2(A + (gr+8) * 136 + kk*16 + tc*2);
            uint32_t a2 = ldh2(A + gr * 136 + kk*16 + tc*2 + 8);
            uint32_t a3 = ldh2(A + (gr+8) * 136 + kk*16 + tc*2 + 8);
            #pragma unroll
            for (int nt = 0; nt < 8; nt++) {
                const __half* Bp = Xs + (nh*64 + nt*8 + gr) * 136 + kk*16 + tc*2;
                uint32_t b0 = ldh2(Bp), b1 = ldh2(Bp + 8);
                mma16816(cK[nt][0], cK[nt][1], cK[nt][2], cK[nt][3],
                         a0, a1, a2, a3, b0, b1);
            }
        }
    }
    #pragma unroll
    for (int nt = 0; nt < 8; nt++) {
        int sl = nh*64 + nt*8 + tc*2;
        int il = mt*16 + gr;
        St[sl * 72 + il]       = __float2half(cK[nt][0]);
        St[(sl+1) * 72 + il]   = __float2half(cK[nt][1]);
        St[sl * 72 + il + 8]   = __float2half(cK[nt][2]);
        St[(sl+1) * 72 + il+8] = __float2half(cK[nt][3]);
    }
    __syncthreads();
    {
        __half* kout = g_kh + (size_t)gb * SSQ * CCH;
        #pragma unroll
        for (int r = 0; r < 4; r++) {
            int id = tid + 256 * r;          // 0..1023
            int row = id >> 3, q = id & 7;
            *(uint4*)(kout + (size_t)(s0 + row) * CCH + i1 + q * 8) =
                *(const uint4*)(St + row * 72 + q * 8);
        }
    }

    // ---- V = Wv @ X^T ----
    float cV[8][4] = {};
    {
        const __half* A = Wv + (mt * 16) * 136;
        #pragma unroll
        for (int kk = 0; kk < 8; kk++) {
            uint32_t a0 = ldh2(A + gr * 136 + kk*16 + tc*2);
            uint32_t a1 = ldh2(A + (gr+8) * 136 + kk*16 + tc*2);
            uint32_t a2 = ldh2(A + gr * 136 + kk*16 + tc*2 + 8);
            uint32_t a3 = ldh2(A + (gr+8) * 136 + kk*16 + tc*2 + 8);
            #pragma unroll
            for (int nt = 0; nt < 8; nt++) {
                const __half* Bp = Xs + (nh*64 + nt*8 + gr) * 136 + kk*16 + tc*2;
                uint32_t b0 = ldh2(Bp), b1 = ldh2(Bp + 8);
                mma16816(cV[nt][0], cV[nt][1], cV[nt][2], cV[nt][3],
                         a0, a1, a2, a3, b0, b1);
            }
        }
    }
    __syncthreads();
    #pragma unroll
    for (int nt = 0; nt < 8; nt++) {
        int sl = nh*64 + nt*8 + tc*2;
        int il = mt*16 + gr;
        *(__half2*)(St + il * 136 + sl)       = __floats2half2_rn(cV[nt][0], cV[nt][1]);
        *(__half2*)(St + (il+8) * 136 + sl)   = __floats2half2_rn(cV[nt][2], cV[nt][3]);
    }
    __syncthreads();
    {
        __half* vout = g_vh + (size_t)gb * CCH * SSQ;
        #pragma unroll
        for (int r = 0; r < 4; r++) {
            int id = tid + 256 * r;          // 0..1023
            int row = id >> 4, q = id & 15;
            *(uint4*)(vout + (size_t)(i1 + row) * SSQ + s0 + q * 8) =
                *(const uint4*)(St + row * 136 + q * 8);
        }
    }
}

// ---------------------------------------------------------------------------
// Q projection (fp32). grid (24 gp, 2 l-half, 2 i-half) = 96 CTAs.
__global__ void proj_q_kernel(const float* __restrict__ proto,
                              const float* __restrict__ qw) {
    __shared__ float Ps[CCH][33];    // [c][l_local]
    __shared__ float Ws[64][17];
    int gp = blockIdx.x;             // 0..23
    int g = gp >> 3;
    int lb = blockIdx.y * 32;
    int i0 = blockIdx.z * 64;
    int tid = threadIdx.x;
    const float* pg  = proto + (size_t)gp * CCH * LLQ;
    const float* qwg = qw + (size_t)g * CCH * CCH;

    #pragma unroll
    for (int r = 0; r < 16; r++) {
        int id = tid + 256 * r;      // 0..4095
        int c = id >> 5, l_ = id & 31;
        Ps[c][l_] = pg[c * LLQ + lb + l_];
    }

    int l = tid & 31, ig = tid >> 5;
    float acc[8] = {};

    for (int c0 = 0; c0 < CCH; c0 += 16) {
        #pragma unroll
        for (int r = 0; r < 4; r++) {
            int id = tid + 256 * r;  // 0..1023
            Ws[id >> 4][id & 15] = qwg[(i0 + (id >> 4)) * CCH + c0 + (id & 15)];
        }
        __syncthreads();
        float pc[16];
        #pragma unroll
        for (int cc = 0; cc < 16; cc++) pc[cc] = Ps[c0 + cc][l];
        #pragma unroll
        for (int r = 0; r < 8; r++) {
            float a = acc[r];
            #pragma unroll
            for (int cc = 0; cc < 16; cc++) a += Ws[ig + 8*r][cc] * pc[cc];
            acc[r] = a;
        }
        __syncthreads();
    }
    float* qo = g_q + (size_t)gp * LLQ * CCH;
    #pragma unroll
    for (int r = 0; r < 8; r++)
        qo[(lb + l) * CCH + i0 + ig + 8*r] = acc[r];
}

// ---------------------------------------------------------------------------
// Fused flash attention. One CTA per (g,b,h,p,lc), 32 L-rows, 8 warps.
// exp in fp32 (__expf); Z via ones-row mma (tensor pipe).
//
// smem (bytes):
//   K dbuf  @0      : 2 x [128][40]h      = 20480
//   V dbuf  @20480  : 2 x [40][136]h      = 21760  (rows 32..39: ones/zeros)
//   E       @42240  : [32][1032]h         = 66048
//   out_sf  @108288 : [32][33]f           = 4224
//   zsh @112512 (128), iz @112640 (128), red @112768 (32)
#define AT_K     0
#define AT_V     20480
#define AT_E     42240
#define AT_OUT   108288
#define AT_ZS    112512
#define AT_IZ    112640
#define AT_RED   112768
#define AT_TOT   112800
#define KBUF_H   5120     // K buffer stride (halfs) = 128*40
#define VBUF_H   5440     // V buffer stride (halfs) = 40*136
#define EST      1032
#define KST      40
#define VST      136

__global__ void __launch_bounds__(256, 2) attn_kernel() {
    extern __shared__ char smraw[];
    __half* Kb   = (__half*)(smraw + AT_K);
    __half* Vb   = (__half*)(smraw + AT_V);
    __half* E    = (__half*)(smraw + AT_E);
    float* out_sf= (float*)(smraw + AT_OUT);   // [32][33]
    float* zsh   = (float*)(smraw + AT_ZS);
    float* iz    = (float*)(smraw + AT_IZ);
    float* red   = (float*)(smraw + AT_RED);

    int idx = blockIdx.x;                  // 1536 = g(3) b(8) h(4) p(8) lc(2)
    int lc = idx & 1, p = (idx >> 1) & 7, h = (idx >> 4) & 3,
        b = (idx >> 6) & 7, g = idx >> 9;
    int tid = threadIdx.x, lane = tid & 31, w = tid >> 5;
    int gr = lane >> 2, tc = lane & 3;
    int lbase = lc * 32;

    const __half* Kg = g_kh + (size_t)(g*BB + b) * SSQ * CCH + h * DH;   // [s][128]+off
    const __half* Vg = g_vh + ((size_t)((g*BB + b) * CCH) + h * DH) * SSQ;
    const float*  Qg = g_q  + (size_t)(g*PP + p) * LLQ * CCH;

    // zero reduction buffers
    #pragma unroll
    for (int r = 0; r < 5; r++) {
        int id = tid + 256 * r;
        if (id < 1056) out_sf[id] = 0.f;
    }
    if (tid < 32) zsh[tid] = 0.f;
    // init V extra rows (32 = ones, 33..39 = zeros) in BOTH buffers
    for (int id = tid; id < 2 * 8 * VST; id += 256) {
        int buf = id / (8 * VST);
        int rem = id - buf * 8 * VST;
        int rrow = rem / VST, cc = rem % VST;
        Vb[buf * VBUF_H + (32 + rrow) * VST + cc] =
            (rrow == 0) ? __float2half(1.f) : __float2half(0.f);
    }

    int mh = w >> 2;                       // row half: rows mh*16..+16
    int ng = w & 3;                        // s-block of 32 within 128-s tile
    int r_lo = mh * 16 + gr, r_hi = r_lo + 8;

    // A fragments for QK from global q (fp32 -> half2)
    uint32_t aq[2][4];
    {
        const float* q0 = Qg + (size_t)(lbase + r_lo) * CCH + h * DH;
        const float* q1 = q0 + 8 * CCH;
        #pragma unroll
        for (int ks = 0; ks < 2; ks++) {
            float2 f0 = *(const float2*)(q0 + ks*16 + tc*2);
            float2 f1 = *(const float2*)(q1 + ks*16 + tc*2);
            float2 f2 = *(const float2*)(q0 + ks*16 + tc*2 + 8);
            float2 f3 = *(const float2*)(q1 + ks*16 + tc*2 + 8);
            aq[ks][0] = packh2(f0.x, f0.y);
            aq[ks][1] = packh2(f1.x, f1.y);
            aq[ks][2] = packh2(f2.x, f2.y);
            aq[ks][3] = packh2(f3.x, f3.y);
        }
    }

    auto loadK = [&](int st, int bf) {
        const __half* src = Kg + (size_t)st * 128 * CCH;
        __half* dst = Kb + bf * KBUF_H;
        #pragma unroll
        for (int it = 0; it < 2; it++) {
            int id = tid + 256 * it;       // 0..511
            int r = id >> 2, ch = id & 3;
            *(uint4*)(dst + r * KST + ch * 8) =
                *(const uint4*)(src + (size_t)r * CCH + ch * 8);
        }
    };
    auto loadV = [&](int st, int bf) {
        const __half* src = Vg + st * 128;
        __half* dst = Vb + bf * VBUF_H;
        #pragma unroll
        for (int it = 0; it < 2; it++) {
            int id = tid + 256 * it;       // 0..511
            int d = id >> 4, ch = id & 15;
            *(uint4*)(dst + d * VST + ch * 8) =
                *(const uint4*)(src + (size_t)d * SSQ + ch * 8);
        }
    };

    loadK(0, 0);
    loadV(0, 0);

    float pv[5][4] = {};                   // nd 0..3: out tiles; nd 4: Z (ones row)

    for (int st = 0; st < 8; st++) {
        __syncthreads();
        if (st < 7) { loadK(st + 1, (st + 1) & 1); loadV(st + 1, (st + 1) & 1); }
        const __half* Kt = Kb + (st & 1) * KBUF_H;
        const __half* Vt = Vb + (st & 1) * VBUF_H;

        #pragma unroll
        for (int j = 0; j < 2; j++) {      // two 16-s k-blocks within warp's 32 s
            uint32_t a0, a1, a2, a3;       // PV A fragments = exp(QK) in fp16
            // ---- nt = 2j ----
            {
                float c0 = 0.f, c1 = 0.f, c2 = 0.f, c3 = 0.f;
                const __half* kb = Kt + (ng*32 + (2*j)*8 + gr) * KST;
                #pragma unroll
                for (int ks = 0; ks < 2; ks++) {
                    uint32_t b0 = ldh2(kb + ks*16 + tc*2);
                    uint32_t b1 = ldh2(kb + ks*16 + tc*2 + 8);
                    mma16816(c0, c1, c2, c3,
                             aq[ks][0], aq[ks][1], aq[ks][2], aq[ks][3], b0, b1);
                }
                float e0 = __expf(c0 * SCALE_F), e1 = __expf(c1 * SCALE_F);
                float e2 = __expf(c2 * SCALE_F), e3 = __expf(c3 * SCALE_F);
                a0 = packh2(e0, e1);
                a1 = packh2(e2, e3);
                int scol = st*128 + ng*32 + (2*j)*8 + tc*2;
                *(uint32_t*)&E[r_lo * EST + scol] = a0;
                *(uint32_t*)&E[r_hi * EST + scol] = a1;
            }
            // ---- nt = 2j+1 ----
            {
                float c0 = 0.f, c1 = 0.f, c2 = 0.f, c3 = 0.f;
                const __half* kb = Kt + (ng*32 + (2*j+1)*8 + gr) * KST;
                #pragma unroll
                for (int ks = 0; ks < 2; ks++) {
                    uint32_t b0 = ldh2(kb + ks*16 + tc*2);
                    uint32_t b1 = ldh2(kb + ks*16 + tc*2 + 8);
                    mma16816(c0, c1, c2, c3,
                             aq[ks][0], aq[ks][1], aq[ks][2], aq[ks][3], b0, b1);
                }
                float e0 = __expf(c0 * SCALE_F), e1 = __expf(c1 * SCALE_F);
                float e2 = __expf(c2 * SCALE_F), e3 = __expf(c3 * SCALE_F);
                a2 = packh2(e0, e1);
                a3 = packh2(e2, e3);
                int scol = st*128 + ng*32 + (2*j+1)*8 + tc*2;
                *(uint32_t*)&E[r_lo * EST + scol] = a2;
                *(uint32_t*)&E[r_hi * EST + scol] = a3;
            }
            // ---- PV + Z: nd 0..3 = out, nd 4 hits the ones row (d=32) ----
            int sloc = ng*32 + j*16 + tc*2;
            #pragma unroll
            for (int nd = 0; nd < 5; nd++) {
                const __half* vbp = Vt + (nd*8 + gr) * VST + sloc;
                uint32_t b0 = ldh2(vbp);
                uint32_t b1 = ldh2(vbp + 8);
                mma16816(pv[nd][0], pv[nd][1], pv[nd][2], pv[nd][3],
                         a0, a1, a2, a3, b0, b1);
            }
        }
    }
    __syncthreads();                       // compute done, E complete

    // ---- Z: pv[4][0]/[2] at tc==0 hold row sums over this warp's s-slice ----
    if (tc == 0) {
        atomicAdd(&zsh[r_lo], pv[4][0]);
        atomicAdd(&zsh[r_hi], pv[4][2]);
    }
    // ---- out partial reduction across ng-warps ----
    #pragma unroll
    for (int nd = 0; nd < 4; nd++) {
        int d = nd*8 + tc*2;
        atomicAdd(&out_sf[r_lo*33 + d],     pv[nd][0]);
        atomicAdd(&out_sf[r_lo*33 + d + 1], pv[nd][1]);
        atomicAdd(&out_sf[r_hi*33 + d],     pv[nd][2]);
        atomicAdd(&out_sf[r_hi*33 + d + 1], pv[nd][3]);
    }
    __syncthreads();
    if (tid < 32) iz[tid] = 1.f / zsh[tid];
    __syncthreads();

    // ---- heat (uint2 loads: 4 s-columns per thread) ----
    float* hout = g_heat + (size_t)((g*BB + b) * PP + p) * SSQ;
    {
        int scol = tid * 4;
        float hs0 = 0.f, hs1 = 0.f, hs2 = 0.f, hs3 = 0.f;
        #pragma unroll
        for (int r = 0; r < 32; r++) {
            uint2 u = *(const uint2*)&E[r * EST + scol];
            float2 fa = __half22float2(reinterpret_cast<__half2&>(u.x));
            float2 fb = __half22float2(reinterpret_cast<__half2&>(u.y));
            float izr = iz[r];
            hs0 += fa.x * izr; hs1 += fa.y * izr;
            hs2 += fb.x * izr; hs3 += fb.y * izr;
        }
        atomicAdd(&hout[scol],     hs0);
        atomicAdd(&hout[scol + 1], hs1);
        atomicAdd(&hout[scol + 2], hs2);
        atomicAdd(&hout[scol + 3], hs3);
    }

    // ---- dist ----
    float dacc = 0.f;
    #pragma unroll
    for (int r = 0; r < 4; r++) {
        int id = tid + 256 * r;            // 0..1023
        int row = id >> 5, d = id & 31;
        float o = out_sf[row*33 + d] * iz[row];
        float qv = Qg[(size_t)(lbase + row) * CCH + h * DH + d];
        float e = qv - o;
        dacc += e * e;
    }
    #pragma unroll
    for (int o = 16; o; o >>= 1) dacc += __shfl_xor_sync(0xffffffffu, dacc, o);
    if (lane == 0) red[w] = dacc;
    __syncthreads();
    if (w == 0) {
        float v = (lane < 8) ? red[lane] : 0.f;
        #pragma unroll
        for (int o = 4; o; o >>= 1) v += __shfl_xor_sync(0xffffffffu, v, o);
        if (lane == 0) atomicAdd(&g_dist[(g*BB + b) * PP + p], v);
    }
}

// ---------------------------------------------------------------------------
// Finalize: dist/(64*128) and argmax(heat) -> out = [dist(8x24) | idx(8x24)]
__global__ void finalize_kernel(float* __restrict__ out, int out_size) {
    __shared__ float bv[128];
    __shared__ int  bidx[128];
    int gbp = blockIdx.x;
    int tid = threadIdx.x;
    const float* hrow = g_heat + (size_t)gbp * SSQ;
    float best = -1e30f; int bi = 0;
    for (int j = tid; j < SSQ; j += 128) {
        float v = hrow[j];
        if (v > best) { best = v; bi = j; }
    }
    bv[tid] = best; bidx[tid] = bi;
    __syncthreads();
    for (int s = 64; s; s >>= 1) {
        if (tid < s) {
            if (bv[tid + s] > bv[tid] ||
                (bv[tid + s] == bv[tid] && bidx[tid + s] < bidx[tid])) {
                bv[tid] = bv[tid + s]; bidx[tid] = bidx[tid + s];
            }
        }
        __syncthreads();
    }
    if (tid == 0) {
        int g = gbp >> 6, b = (gbp >> 3) & 7, p = gbp & 7;
        int col = g * PP + p;
        out[b * 24 + col] = g_dist[gbp] * (1.f / (64.f * 128.f));
        if (out_size >= 384)
            out[192 + b * 24 + col] = (float)bidx[0];
    }
}

// ---------------------------------------------------------------------------
extern "C" void kernel_launch(void* const* d_in, const int* in_sizes, int n_in,
                              void* d_out, int out_size) {
    const float* x     = (const float*)d_in[0];
    const float* proto = (const float*)d_in[1];
    const float* qw    = (const float*)d_in[2];
    const float* kw    = (const float*)d_in[3];
    const float* vw    = (const float*)d_in[4];
    float* out = (float*)d_out;

    cudaFuncSetAttribute(attn_kernel,
                         cudaFuncAttributeMaxDynamicSharedMemorySize, AT_TOT);
    cudaFuncSetAttribute(proj_kv_mma_kernel,
                         cudaFuncAttributeMaxDynamicSharedMemorySize, PJ_TOT);

    prep_kernel<<<768, 256>>>(kw, vw);
    convert_x_kernel<<<dim3(16, 2, 8), 256>>>(x);
    proj_kv_mma_kernel<<<dim3(8, 2, 24), 256, PJ_TOT>>>();
    proj_q_kernel<<<dim3(24, 2, 2), 256>>>(proto, qw);
    attn_kernel<<<1536, 256, AT_TOT>>>();
    finalize_kernel<<<192, 128>>>(out, out_size);
}

// round 10
// speedup vs baseline: 4.2771x; 1.0972x over previous
#include <cuda_runtime.h>
#include <cuda_fp16.h>
#include <cstdint>

#define NG 3
#define PP 8
#define BB 8
#define CCH 128
#define SSQ 1024
#define LLQ 64
#define HH 4
#define DH 32
#define SCALE_F 0.17677669529663687f

// Scratch (static __device__ arrays: allocation-free per harness rules)
__device__ __align__(256) __half g_xh [BB*SSQ*CCH];     // [b][s][c]  fp16
__device__ __align__(256) __half g_wkh[NG*CCH*CCH];     // [g][i][c]  fp16
__device__ __align__(256) __half g_wvh[NG*CCH*CCH];     // [g][i][c]  fp16
__device__ __align__(256) __half g_kh[NG*BB*SSQ*CCH];   // [g][b][s][c]  fp16
__device__ __align__(256) __half g_vh[NG*BB*CCH*SSQ];   // [g][b][c][s]  fp16
__device__ __align__(256) float  g_q [NG*PP*LLQ*CCH];   // [g][p][l][i]  fp32
__device__ __align__(256) float  g_heat[NG*BB*PP*SSQ];  // [g][b][p][s]
__device__ float g_dist[NG*BB*PP];                      // [g][b][p]

__device__ __forceinline__ void mma16816(float& c0, float& c1, float& c2, float& c3,
                                         uint32_t a0, uint32_t a1, uint32_t a2, uint32_t a3,
                                         uint32_t b0, uint32_t b1) {
    asm volatile("mma.sync.aligned.m16n8k16.row.col.f32.f16.f16.f32 "
                 "{%0,%1,%2,%3},{%4,%5,%6,%7},{%8,%9},{%0,%1,%2,%3};"
                 : "+f"(c0), "+f"(c1), "+f"(c2), "+f"(c3)
                 : "r"(a0), "r"(a1), "r"(a2), "r"(a3), "r"(b0), "r"(b1));
}
__device__ __forceinline__ uint32_t ldh2(const __half* p) {
    return *reinterpret_cast<const uint32_t*>(p);
}
__device__ __forceinline__ uint32_t packh2(float a, float b) {
    __half2 h = __floats2half2_rn(a, b);
    return reinterpret_cast<uint32_t&>(h);
}

// ---------------------------------------------------------------------------
// prep: zero heat/dist + convert weights to fp16. grid 768 x 256.
__global__ void prep_kernel(const float* __restrict__ kw,
                            const float* __restrict__ vw) {
    int i = blockIdx.x * 256 + threadIdx.x;     // 0..196607
    g_heat[i] = 0.f;                             // exactly NG*BB*PP*SSQ
    if (i < NG*BB*PP) g_dist[i] = 0.f;
    if (i < NG*CCH*CCH) {
        g_wkh[i] = __float2half(kw[i]);
        g_wvh[i] = __float2half(vw[i]);
    }
}

// ---------------------------------------------------------------------------
// x [b][c][s] fp32 -> g_xh [b][s][c] fp16 (transpose 64x64 tiles)
__global__ void convert_x_kernel(const float* __restrict__ x) {
    __shared__ float Ts[64][68];
    int b = blockIdx.z, c0 = blockIdx.y * 64, s0 = blockIdx.x * 64;
    int tid = threadIdx.x;
    const float* xb = x + ((size_t)b * CCH + c0) * SSQ + s0;
    #pragma unroll
    for (int r = 0; r < 4; r++) {
        int id = tid + 256 * r;              // 0..1023 float4 units
        int cc = id >> 4, f4 = id & 15;
        float4 v = *(const float4*)(xb + (size_t)cc * SSQ + f4 * 4);
        *(float4*)&Ts[cc][f4 * 4] = v;
    }
    __syncthreads();
    __half* xo = g_xh + ((size_t)b * SSQ + s0) * CCH + c0;
    #pragma unroll
    for (int r = 0; r < 8; r++) {
        int id = tid + 256 * r;              // 0..2047 half2 units
        int ss = id >> 5, cp = id & 31;
        __half2 h = __floats2half2_rn(Ts[cp*2][ss], Ts[cp*2+1][ss]);
        *(__half2*)(xo + (size_t)ss * CCH + cp * 2) = h;
    }
}

// ---------------------------------------------------------------------------
// K/V projection via fp16 mma: out K[s][i], V[i][s] per (g,b).
#define PJ_XS   0
#define PJ_WK   34816
#define PJ_WV   52224
#define PJ_ST   69632
#define PJ_TOT  88064

__global__ void __launch_bounds__(256, 2) proj_kv_mma_kernel() {
    extern __shared__ char smraw[];
    __half* Xs = (__half*)(smraw + PJ_XS);   // [128][136]
    __half* Wk = (__half*)(smraw + PJ_WK);   // [64][136]
    __half* Wv = (__half*)(smraw + PJ_WV);   // [64][136]
    __half* St = (__half*)(smraw + PJ_ST);

    int s0 = blockIdx.x * 128, i1 = blockIdx.y * 64;
    int gb = blockIdx.z;
    int g = gb >> 3, b = gb & 7;
    int tid = threadIdx.x, lane = tid & 31, w = tid >> 5;
    int gr = lane >> 2, tc = lane & 3;
    int mt = w & 3, nh = w >> 2;

    {
        const __half* src = g_xh + ((size_t)b * SSQ + s0) * CCH;
        #pragma unroll
        for (int r = 0; r < 8; r++) {
            int id = tid + 256 * r;          // 0..2047
            int row = id >> 4, q = id & 15;
            *(uint4*)(Xs + row * 136 + q * 8) =
                *(const uint4*)(src + (size_t)row * CCH + q * 8);
        }
        const __half* sk = g_wkh + (size_t)(g * CCH + i1) * CCH;
        const __half* sv = g_wvh + (size_t)(g * CCH + i1) * CCH;
        #pragma unroll
        for (int r = 0; r < 4; r++) {
            int id = tid + 256 * r;          // 0..1023
            int row = id >> 4, q = id & 15;
            *(uint4*)(Wk + row * 136 + q * 8) = *(const uint4*)(sk + (size_t)row * CCH + q * 8);
            *(uint4*)(Wv + row * 136 + q * 8) = *(const uint4*)(sv + (size_t)row * CCH + q * 8);
        }
    }
    __syncthreads();

    // ---- K = Wk @ X^T ----
    float cK[8][4] = {};
    {
        const __half* A = Wk + (mt * 16) * 136;
        #pragma unroll
        for (int kk = 0; kk < 8; kk++) {
            uint32_t a0 = ldh2(A + gr * 136 + kk*16 + tc*2);
            uint32_t a1 = ldh2(A + (gr+8) * 136 + kk*16 + tc*2);
            uint32_t a2 = ldh2(A + gr * 136 + kk*16 + tc*2 + 8);
            uint32_t a3 = ldh2(A + (gr+8) * 136 + kk*16 + tc*2 + 8);
            #pragma unroll
            for (int nt = 0; nt < 8; nt++) {
                const __half* Bp = Xs + (nh*64 + nt*8 + gr) * 136 + kk*16 + tc*2;
                uint32_t b0 = ldh2(Bp), b1 = ldh2(Bp + 8);
                mma16816(cK[nt][0], cK[nt][1], cK[nt][2], cK[nt][3],
                         a0, a1, a2, a3, b0, b1);
            }
        }
    }
    #pragma unroll
    for (int nt = 0; nt < 8; nt++) {
        int sl = nh*64 + nt*8 + tc*2;
        int il = mt*16 + gr;
        St[sl * 72 + il]       = __float2half(cK[nt][0]);
        St[(sl+1) * 72 + il]   = __float2half(cK[nt][1]);
        St[sl * 72 + il + 8]   = __float2half(cK[nt][2]);
        St[(sl+1) * 72 + il+8] = __float2half(cK[nt][3]);
    }
    __syncthreads();
    {
        __half* kout = g_kh + (size_t)gb * SSQ * CCH;
        #pragma unroll
        for (int r = 0; r < 4; r++) {
            int id = tid + 256 * r;          // 0..1023
            int row = id >> 3, q = id & 7;
            *(uint4*)(kout + (size_t)(s0 + row) * CCH + i1 + q * 8) =
                *(const uint4*)(St + row * 72 + q * 8);
        }
    }

    // ---- V = Wv @ X^T ----
    float cV[8][4] = {};
    {
        const __half* A = Wv + (mt * 16) * 136;
        #pragma unroll
        for (int kk = 0; kk < 8; kk++) {
            uint32_t a0 = ldh2(A + gr * 136 + kk*16 + tc*2);
            uint32_t a1 = ldh2(A + (gr+8) * 136 + kk*16 + tc*2);
            uint32_t a2 = ldh2(A + gr * 136 + kk*16 + tc*2 + 8);
            uint32_t a3 = ldh2(A + (gr+8) * 136 + kk*16 + tc*2 + 8);
            #pragma unroll
            for (int nt = 0; nt < 8; nt++) {
                const __half* Bp = Xs + (nh*64 + nt*8 + gr) * 136 + kk*16 + tc*2;
                uint32_t b0 = ldh2(Bp), b1 = ldh2(Bp + 8);
                mma16816(cV[nt][0], cV[nt][1], cV[nt][2], cV[nt][3],
                         a0, a1, a2, a3, b0, b1);
            }
        }
    }
    __syncthreads();
    #pragma unroll
    for (int nt = 0; nt < 8; nt++) {
        int sl = nh*64 + nt*8 + tc*2;
        int il = mt*16 + gr;
        *(__half2*)(St + il * 136 + sl)       = __floats2half2_rn(cV[nt][0], cV[nt][1]);
        *(__half2*)(St + (il+8) * 136 + sl)   = __floats2half2_rn(cV[nt][2], cV[nt][3]);
    }
    __syncthreads();
    {
        __half* vout = g_vh + (size_t)gb * CCH * SSQ;
        #pragma unroll
        for (int r = 0; r < 4; r++) {
            int id = tid + 256 * r;          // 0..1023
            int row = id >> 4, q = id & 15;
            *(uint4*)(vout + (size_t)(i1 + row) * SSQ + s0 + q * 8) =
                *(const uint4*)(St + row * 136 + q * 8);
        }
    }
}

// ---------------------------------------------------------------------------
// Q projection (fp32), single-sync full-smem design.
// grid (24 gp, 4 i-quarters of 32), 256 threads.
// smem: Ps [64 l][132 c] f (33792B) + Ws [32 i][132 c] f (16896B) = 50688B
#define PQ_PS   0
#define PQ_WS   (64*132)
#define PQ_TOT  ((64*132 + 32*132) * 4)

__global__ void __launch_bounds__(256, 2) proj_q_kernel(const float* __restrict__ proto,
                                                        const float* __restrict__ qw) {
    extern __shared__ float smq[];
    float* Ps = smq + PQ_PS;     // [64][132]  (l-major, transposed from proto)
    float* Ws = smq + PQ_WS;     // [32][132]
    int gp = blockIdx.x;         // 0..23
    int g  = gp >> 3;
    int i0 = blockIdx.y * 32;
    int tid = threadIdx.x;
    const float* pg  = proto + (size_t)gp * CCH * LLQ;
    const float* qwg = qw + (size_t)g * CCH * CCH;

    // Ps: transpose [c][l] -> [l][c]
    #pragma unroll
    for (int r = 0; r < 32; r++) {
        int id = tid + 256 * r;        // 0..8191
        int c = id >> 6, l = id & 63;
        Ps[l * 132 + c] = pg[id];
    }
    // Ws: straight copy, float4
    #pragma unroll
    for (int r = 0; r < 4; r++) {
        int id4 = tid + 256 * r;       // 0..1023
        int row = id4 >> 5, c4 = id4 & 31;
        float4 v = *(const float4*)(qwg + (size_t)(i0 + row) * CCH + c4 * 4);
        *(float4*)&Ws[row * 132 + c4 * 4] = v;
    }
    __syncthreads();

    int tx = tid & 15, ty = tid >> 4;
    float acc[4][2] = {};
    #pragma unroll
    for (int c4 = 0; c4 < 32; c4++) {
        float4 wv0 = *(const float4*)&Ws[tx * 132 + c4 * 4];
        float4 wv1 = *(const float4*)&Ws[(tx + 16) * 132 + c4 * 4];
        #pragma unroll
        for (int a = 0; a < 4; a++) {
            float4 pv = *(const float4*)&Ps[(ty + 16*a) * 132 + c4 * 4];
            acc[a][0] += pv.x*wv0.x + pv.y*wv0.y + pv.z*wv0.z + pv.w*wv0.w;
            acc[a][1] += pv.x*wv1.x + pv.y*wv1.y + pv.z*wv1.z + pv.w*wv1.w;
        }
    }
    float* qo = g_q + (size_t)gp * LLQ * CCH;
    #pragma unroll
    for (int a = 0; a < 4; a++) {
        qo[(ty + 16*a) * CCH + i0 + tx]      = acc[a][0];
        qo[(ty + 16*a) * CCH + i0 + tx + 16] = acc[a][1];
    }
}

// ---------------------------------------------------------------------------
// Fused flash attention. One CTA per (g,b,h,p,lc), 32 L-rows, 8 warps.
// Per-pair K/V slice loads + named barriers (pairs = {ng, ng+4}) decouple the
// pipeline; exp fp32; Z via ones-row mma.
#define AT_K     0
#define AT_V     20480
#define AT_E     42240
#define AT_OUT   108288
#define AT_ZS    112512
#define AT_IZ    112640
#define AT_RED   112768
#define AT_TOT   112800
#define KBUF_H   5120     // K buffer stride (halfs) = 128*40
#define VBUF_H   5440     // V buffer stride (halfs) = 40*136
#define EST      1032
#define KST      40
#define VST      136

__global__ void __launch_bounds__(256, 2) attn_kernel() {
    extern __shared__ char smraw[];
    __half* Kb   = (__half*)(smraw + AT_K);
    __half* Vb   = (__half*)(smraw + AT_V);
    __half* E    = (__half*)(smraw + AT_E);
    float* out_sf= (float*)(smraw + AT_OUT);   // [32][33]
    float* zsh   = (float*)(smraw + AT_ZS);
    float* iz    = (float*)(smraw + AT_IZ);
    float* red   = (float*)(smraw + AT_RED);

    int idx = blockIdx.x;                  // 1536 = g(3) b(8) h(4) p(8) lc(2)
    int lc = idx & 1, p = (idx >> 1) & 7, h = (idx >> 4) & 3,
        b = (idx >> 6) & 7, g = idx >> 9;
    int tid = threadIdx.x, lane = tid & 31, w = tid >> 5;
    int gr = lane >> 2, tc = lane & 3;
    int lbase = lc * 32;

    const __half* Kg = g_kh + (size_t)(g*BB + b) * SSQ * CCH + h * DH;   // [s][128]+off
    const __half* Vg = g_vh + ((size_t)((g*BB + b) * CCH) + h * DH) * SSQ;
    const float*  Qg = g_q  + (size_t)(g*PP + p) * LLQ * CCH;

    int mh = w >> 2;                       // row half: rows mh*16..+16
    int ng = w & 3;                        // s-block of 32 within 128-s tile
    int plid = mh * 32 + lane;             // pair-local index 0..63
    int r_lo = mh * 16 + gr, r_hi = r_lo + 8;

    // zero reduction buffers
    #pragma unroll
    for (int r = 0; r < 5; r++) {
        int id = tid + 256 * r;
        if (id < 1056) out_sf[id] = 0.f;
    }
    if (tid < 32) zsh[tid] = 0.f;
    // init V extra rows (32 = ones, 33..39 = zeros) in BOTH buffers
    for (int id = tid; id < 2 * 8 * VST; id += 256) {
        int buf = id / (8 * VST);
        int rem = id - buf * 8 * VST;
        int rrow = rem / VST, cc = rem % VST;
        Vb[buf * VBUF_H + (32 + rrow) * VST + cc] =
            (rrow == 0) ? __float2half(1.f) : __float2half(0.f);
    }

    // A fragments for QK from global q (fp32 -> half2)
    uint32_t aq[2][4];
    {
        const float* q0 = Qg + (size_t)(lbase + r_lo) * CCH + h * DH;
        const float* q1 = q0 + 8 * CCH;
        #pragma unroll
        for (int ks = 0; ks < 2; ks++) {
            float2 f0 = *(const float2*)(q0 + ks*16 + tc*2);
            float2 f1 = *(const float2*)(q1 + ks*16 + tc*2);
            float2 f2 = *(const float2*)(q0 + ks*16 + tc*2 + 8);
            float2 f3 = *(const float2*)(q1 + ks*16 + tc*2 + 8);
            aq[ks][0] = packh2(f0.x, f0.y);
            aq[ks][1] = packh2(f1.x, f1.y);
            aq[ks][2] = packh2(f2.x, f2.y);
            aq[ks][3] = packh2(f3.x, f3.y);
        }
    }

    // Per-pair slice loads: pair ng loads K rows [ng*32,+32) and V cols [ng*32,+32).
    auto loadK = [&](int st, int bf) {
        const __half* src = Kg + (size_t)st * 128 * CCH;
        __half* dst = Kb + bf * KBUF_H;
        #pragma unroll
        for (int it = 0; it < 2; it++) {
            int id = plid + 64 * it;       // 0..127
            int rl = ng*32 + (id >> 2), ch = id & 3;
            *(uint4*)(dst + rl * KST + ch * 8) =
                *(const uint4*)(src + (size_t)rl * CCH + ch * 8);
        }
    };
    auto loadV = [&](int st, int bf) {
        const __half* src = Vg + st * 128 + ng * 32;
        __half* dst = Vb + bf * VBUF_H + ng * 32;
        #pragma unroll
        for (int it = 0; it < 2; it++) {
            int id = plid + 64 * it;       // 0..127
            int d = id >> 2, ch = id & 3;
            *(uint4*)(dst + d * VST + ch * 8) =
                *(const uint4*)(src + (size_t)d * SSQ + ch * 8);
        }
    };

    loadK(0, 0);
    loadV(0, 0);
    __syncthreads();                       // init (ones rows etc.) + prologue visible

    float pv[5][4] = {};                   // nd 0..3: out tiles; nd 4: Z (ones row)

    for (int st = 0; st < 8; st++) {
        if (st > 0)
            asm volatile("bar.sync %0, 64;" :: "r"(ng + 1) : "memory");
        if (st < 7) { loadK(st + 1, (st + 1) & 1); loadV(st + 1, (st + 1) & 1); }
        const __half* Kt = Kb + (st & 1) * KBUF_H;
        const __half* Vt = Vb + (st & 1) * VBUF_H;

        #pragma unroll
        for (int j = 0; j < 2; j++) {      // two 16-s k-blocks within warp's 32 s
            uint32_t a0, a1, a2, a3;       // PV A fragments = exp(QK) in fp16
            // ---- nt = 2j ----
            {
                float c0 = 0.f, c1 = 0.f, c2 = 0.f, c3 = 0.f;
                const __half* kb = Kt + (ng*32 + (2*j)*8 + gr) * KST;
                #pragma unroll
                for (int ks = 0; ks < 2; ks++) {
                    uint32_t b0 = ldh2(kb + ks*16 + tc*2);
                    uint32_t b1 = ldh2(kb + ks*16 + tc*2 + 8);
                    mma16816(c0, c1, c2, c3,
                             aq[ks][0], aq[ks][1], aq[ks][2], aq[ks][3], b0, b1);
                }
                float e0 = __expf(c0 * SCALE_F), e1 = __expf(c1 * SCALE_F);
                float e2 = __expf(c2 * SCALE_F), e3 = __expf(c3 * SCALE_F);
                a0 = packh2(e0, e1);
                a1 = packh2(e2, e3);
                int scol = st*128 + ng*32 + (2*j)*8 + tc*2;
                *(uint32_t*)&E[r_lo * EST + scol] = a0;
                *(uint32_t*)&E[r_hi * EST + scol] = a1;
            }
            // ---- nt = 2j+1 ----
            {
                float c0 = 0.f, c1 = 0.f, c2 = 0.f, c3 = 0.f;
                const __half* kb = Kt + (ng*32 + (2*j+1)*8 + gr) * KST;
                #pragma unroll
                for (int ks = 0; ks < 2; ks++) {
                    uint32_t b0 = ldh2(kb + ks*16 + tc*2);
                    uint32_t b1 = ldh2(kb + ks*16 + tc*2 + 8);
                    mma16816(c0, c1, c2, c3,
                             aq[ks][0], aq[ks][1], aq[ks][2], aq[ks][3], b0, b1);
                }
                float e0 = __expf(c0 * SCALE_F), e1 = __expf(c1 * SCALE_F);
                float e2 = __expf(c2 * SCALE_F), e3 = __expf(c3 * SCALE_F);
                a2 = packh2(e0, e1);
                a3 = packh2(e2, e3);
                int scol = st*128 + ng*32 + (2*j+1)*8 + tc*2;
                *(uint32_t*)&E[r_lo * EST + scol] = a2;
                *(uint32_t*)&E[r_hi * EST + scol] = a3;
            }
            // ---- PV + Z: nd 0..3 = out, nd 4 hits the ones row (d=32) ----
            int sloc = ng*32 + j*16 + tc*2;
            #pragma unroll
            for (int nd = 0; nd < 5; nd++) {
                const __half* vbp = Vt + (nd*8 + gr) * VST + sloc;
                uint32_t b0 = ldh2(vbp);
                uint32_t b1 = ldh2(vbp + 8);
                mma16816(pv[nd][0], pv[nd][1], pv[nd][2], pv[nd][3],
                         a0, a1, a2, a3, b0, b1);
            }
        }
    }

    // ---- Z: pv[4][0]/[2] at tc==0 hold row sums over this warp's s-slice ----
    if (tc == 0) {
        atomicAdd(&zsh[r_lo], pv[4][0]);
        atomicAdd(&zsh[r_hi], pv[4][2]);
    }
    // ---- out partial reduction across ng-warps ----
    #pragma unroll
    for (int nd = 0; nd < 4; nd++) {
        int d = nd*8 + tc*2;
        atomicAdd(&out_sf[r_lo*33 + d],     pv[nd][0]);
        atomicAdd(&out_sf[r_lo*33 + d + 1], pv[nd][1]);
        atomicAdd(&out_sf[r_hi*33 + d],     pv[nd][2]);
        atomicAdd(&out_sf[r_hi*33 + d + 1], pv[nd][3]);
    }
    __syncthreads();                       // E complete + zsh/out atomics done
    if (tid < 32) iz[tid] = 1.f / zsh[tid];
    __syncthreads();

    // ---- heat (uint2 loads: 4 s-columns per thread) ----
    float* hout = g_heat + (size_t)((g*BB + b) * PP + p) * SSQ;
    {
        int scol = tid * 4;
        float hs0 = 0.f, hs1 = 0.f, hs2 = 0.f, hs3 = 0.f;
        #pragma unroll
        for (int r = 0; r < 32; r++) {
            uint2 u = *(const uint2*)&E[r * EST + scol];
            float2 fa = __half22float2(reinterpret_cast<__half2&>(u.x));
            float2 fb = __half22float2(reinterpret_cast<__half2&>(u.y));
            float izr = iz[r];
            hs0 += fa.x * izr; hs1 += fa.y * izr;
            hs2 += fb.x * izr; hs3 += fb.y * izr;
        }
        atomicAdd(&hout[scol],     hs0);
        atomicAdd(&hout[scol + 1], hs1);
        atomicAdd(&hout[scol + 2], hs2);
        atomicAdd(&hout[scol + 3], hs3);
    }

    // ---- dist ----
    float dacc = 0.f;
    #pragma unroll
    for (int r = 0; r < 4; r++) {
        int id = tid + 256 * r;            // 0..1023
        int row = id >> 5, d = id & 31;
        float o = out_sf[row*33 + d] * iz[row];
        float qv = Qg[(size_t)(lbase + row) * CCH + h * DH + d];
        float e = qv - o;
        dacc += e * e;
    }
    #pragma unroll
    for (int o = 16; o; o >>= 1) dacc += __shfl_xor_sync(0xffffffffu, dacc, o);
    if (lane == 0) red[w] = dacc;
    __syncthreads();
    if (w == 0) {
        float v = (lane < 8) ? red[lane] : 0.f;
        #pragma unroll
        for (int o = 4; o; o >>= 1) v += __shfl_xor_sync(0xffffffffu, v, o);
        if (lane == 0) atomicAdd(&g_dist[(g*BB + b) * PP + p], v);
    }
}

// ---------------------------------------------------------------------------
// Finalize: dist/(64*128) and argmax(heat) -> out = [dist(8x24) | idx(8x24)]
__global__ void finalize_kernel(float* __restrict__ out, int out_size) {
    __shared__ float bv[128];
    __shared__ int  bidx[128];
    int gbp = blockIdx.x;
    int tid = threadIdx.x;
    const float* hrow = g_heat + (size_t)gbp * SSQ;
    float best = -1e30f; int bi = 0;
    for (int j = tid; j < SSQ; j += 128) {
        float v = hrow[j];
        if (v > best) { best = v; bi = j; }
    }
    bv[tid] = best; bidx[tid] = bi;
    __syncthreads();
    for (int s = 64; s; s >>= 1) {
        if (tid < s) {
            if (bv[tid + s] > bv[tid] ||
                (bv[tid + s] == bv[tid] && bidx[tid + s] < bidx[tid])) {
                bv[tid] = bv[tid + s]; bidx[tid] = bidx[tid + s];
            }
        }
        __syncthreads();
    }
    if (tid == 0) {
        int g = gbp >> 6, b = (gbp >> 3) & 7, p = gbp & 7;
        int col = g * PP + p;
        out[b * 24 + col] = g_dist[gbp] * (1.f / (64.f * 128.f));
        if (out_size >= 384)
            out[192 + b * 24 + col] = (float)bidx[0];
    }
}

// ---------------------------------------------------------------------------
extern "C" void kernel_launch(void* const* d_in, const int* in_sizes, int n_in,
                              void* d_out, int out_size) {
    const float* x     = (const float*)d_in[0];
    const float* proto = (const float*)d_in[1];
    const float* qw    = (const float*)d_in[2];
    const float* kw    = (const float*)d_in[3];
    const float* vw    = (const float*)d_in[4];
    float* out = (float*)d_out;

    cudaFuncSetAttribute(attn_kernel,
                         cudaFuncAttributeMaxDynamicSharedMemorySize, AT_TOT);
    cudaFuncSetAttribute(proj_kv_mma_kernel,
                         cudaFuncAttributeMaxDynamicSharedMemorySize, PJ_TOT);
    cudaFuncSetAttribute(proj_q_kernel,
                         cudaFuncAttributeMaxDynamicSharedMemorySize, PQ_TOT);

    prep_kernel<<<768, 256>>>(kw, vw);
    convert_x_kernel<<<dim3(16, 2, 8), 256>>>(x);
    proj_kv_mma_kernel<<<dim3(8, 2, 24), 256, PJ_TOT>>>();
    proj_q_kernel<<<dim3(24, 4), 256, PQ_TOT>>>(proto, qw);
    attn_kernel<<<1536, 256, AT_TOT>>>();
    finalize_kernel<<<192, 128>>>(out, out_size);
}

// round 11
// speedup vs baseline: 4.4320x; 1.0362x over previous
#include <cuda_runtime.h>
#include <cuda_fp16.h>
#include <cstdint>

#define NG 3
#define PP 8
#define BB 8
#define CCH 128
#define SSQ 1024
#define LLQ 64
#define HH 4
#define DH 32
#define SCALE_F 0.17677669529663687f

// Scratch (static __device__ arrays: allocation-free per harness rules)
__device__ __align__(256) __half g_xh [BB*SSQ*CCH];     // [b][s][c]  fp16
__device__ __align__(256) __half g_wkh[NG*CCH*CCH];     // [g][i][c]  fp16
__device__ __align__(256) __half g_wvh[NG*CCH*CCH];     // [g][i][c]  fp16
__device__ __align__(256) __half g_kh[NG*BB*SSQ*CCH];   // [g][b][s][c]  fp16
__device__ __align__(256) __half g_vh[NG*BB*CCH*SSQ];   // [g][b][c][s]  fp16
__device__ __align__(256) float  g_q [NG*PP*LLQ*CCH];   // [g][p][l][i]  fp32
__device__ __align__(256) float  g_heat[NG*BB*PP*SSQ];  // [g][b][p][s]
__device__ float g_dist[NG*BB*PP];                      // [g][b][p]

__device__ __forceinline__ void mma16816(float& c0, float& c1, float& c2, float& c3,
                                         uint32_t a0, uint32_t a1, uint32_t a2, uint32_t a3,
                                         uint32_t b0, uint32_t b1) {
    asm volatile("mma.sync.aligned.m16n8k16.row.col.f32.f16.f16.f32 "
                 "{%0,%1,%2,%3},{%4,%5,%6,%7},{%8,%9},{%0,%1,%2,%3};"
                 : "+f"(c0), "+f"(c1), "+f"(c2), "+f"(c3)
                 : "r"(a0), "r"(a1), "r"(a2), "r"(a3), "r"(b0), "r"(b1));
}
__device__ __forceinline__ uint32_t ldh2(const __half* p) {
    return *reinterpret_cast<const uint32_t*>(p);
}
__device__ __forceinline__ uint32_t packh2(float a, float b) {
    __half2 h = __floats2half2_rn(a, b);
    return reinterpret_cast<uint32_t&>(h);
}

// ---------------------------------------------------------------------------
// Fused prologue: one launch, three independent jobs branched on blockIdx.x.
//   CTAs [0,768)    : zero heat/dist + convert weights to fp16
//   CTAs [768,1024) : x [b][c][s] fp32 -> g_xh [b][s][c] fp16 (64x64 transpose)
//   CTAs [1024,1120): q projection (fp32), single-sync full-smem GEMM
// Dyn smem = max(proj_q 50688, convert_x 17408) = 50688 B.
#define PQ_PS   0
#define PQ_WS   (64*132)
#define FP_TOT  ((64*132 + 32*132) * 4)

__global__ void __launch_bounds__(256, 2) fused_pre_kernel(
        const float* __restrict__ x,     const float* __restrict__ proto,
        const float* __restrict__ qw,    const float* __restrict__ kw,
        const float* __restrict__ vw) {
    extern __shared__ float smq[];
    int bid = blockIdx.x;
    int tid = threadIdx.x;

    if (bid < 768) {
        // ---------------- prep ----------------
        int i = bid * 256 + tid;                 // 0..196607
        g_heat[i] = 0.f;                          // exactly NG*BB*PP*SSQ
        if (i < NG*BB*PP) g_dist[i] = 0.f;
        if (i < NG*CCH*CCH) {
            g_wkh[i] = __float2half(kw[i]);
            g_wvh[i] = __float2half(vw[i]);
        }
        return;
    }
    if (bid < 1024) {
        // ---------------- convert_x ----------------
        int cb = bid - 768;                      // 0..255
        int s0 = (cb & 15) * 64;
        int c0 = ((cb >> 4) & 1) * 64;
        int b  = cb >> 5;
        float* Ts = smq;                         // [64][68]
        const float* xb = x + ((size_t)b * CCH + c0) * SSQ + s0;
        #pragma unroll
        for (int r = 0; r < 4; r++) {
            int id = tid + 256 * r;              // 0..1023 float4 units
            int cc = id >> 4, f4 = id & 15;
            float4 v = *(const float4*)(xb + (size_t)cc * SSQ + f4 * 4);
            *(float4*)&Ts[cc * 68 + f4 * 4] = v;
        }
        __syncthreads();
        __half* xo = g_xh + ((size_t)b * SSQ + s0) * CCH + c0;
        #pragma unroll
        for (int r = 0; r < 8; r++) {
            int id = tid + 256 * r;              // 0..2047 half2 units
            int ss = id >> 5, cp = id & 31;
            __half2 h = __floats2half2_rn(Ts[(cp*2) * 68 + ss], Ts[(cp*2+1) * 68 + ss]);
            *(__half2*)(xo + (size_t)ss * CCH + cp * 2) = h;
        }
        return;
    }
    // ---------------- proj_q ----------------
    {
        int qb = bid - 1024;                     // 0..95
        int gp = qb % 24;
        int i0 = (qb / 24) * 32;
        int g  = gp >> 3;
        float* Ps = smq + PQ_PS;                 // [64][132]  (l-major)
        float* Ws = smq + PQ_WS;                 // [32][132]
        const float* pg  = proto + (size_t)gp * CCH * LLQ;
        const float* qwg = qw + (size_t)g * CCH * CCH;

        #pragma unroll
        for (int r = 0; r < 32; r++) {
            int id = tid + 256 * r;              // 0..8191
            int c = id >> 6, l = id & 63;
            Ps[l * 132 + c] = pg[id];
        }
        #pragma unroll
        for (int r = 0; r < 4; r++) {
            int id4 = tid + 256 * r;             // 0..1023
            int row = id4 >> 5, c4 = id4 & 31;
            float4 v = *(const float4*)(qwg + (size_t)(i0 + row) * CCH + c4 * 4);
            *(float4*)&Ws[row * 132 + c4 * 4] = v;
        }
        __syncthreads();

        int tx = tid & 15, ty = tid >> 4;
        float acc[4][2] = {};
        #pragma unroll
        for (int c4 = 0; c4 < 32; c4++) {
            float4 wv0 = *(const float4*)&Ws[tx * 132 + c4 * 4];
            float4 wv1 = *(const float4*)&Ws[(tx + 16) * 132 + c4 * 4];
            #pragma unroll
            for (int a = 0; a < 4; a++) {
                float4 pv = *(const float4*)&Ps[(ty + 16*a) * 132 + c4 * 4];
                acc[a][0] += pv.x*wv0.x + pv.y*wv0.y + pv.z*wv0.z + pv.w*wv0.w;
                acc[a][1] += pv.x*wv1.x + pv.y*wv1.y + pv.z*wv1.z + pv.w*wv1.w;
            }
        }
        float* qo = g_q + (size_t)gp * LLQ * CCH;
        #pragma unroll
        for (int a = 0; a < 4; a++) {
            qo[(ty + 16*a) * CCH + i0 + tx]      = acc[a][0];
            qo[(ty + 16*a) * CCH + i0 + tx + 16] = acc[a][1];
        }
    }
}

// ---------------------------------------------------------------------------
// K/V projection via fp16 mma: out K[s][i], V[i][s] per (g,b).
#define PJ_XS   0
#define PJ_WK   34816
#define PJ_WV   52224
#define PJ_ST   69632
#define PJ_TOT  88064

__global__ void __launch_bounds__(256, 2) proj_kv_mma_kernel() {
    extern __shared__ char smraw[];
    __half* Xs = (__half*)(smraw + PJ_XS);   // [128][136]
    __half* Wk = (__half*)(smraw + PJ_WK);   // [64][136]
    __half* Wv = (__half*)(smraw + PJ_WV);   // [64][136]
    __half* St = (__half*)(smraw + PJ_ST);

    int s0 = blockIdx.x * 128, i1 = blockIdx.y * 64;
    int gb = blockIdx.z;
    int g = gb >> 3, b = gb & 7;
    int tid = threadIdx.x, lane = tid & 31, w = tid >> 5;
    int gr = lane >> 2, tc = lane & 3;
    int mt = w & 3, nh = w >> 2;

    {
        const __half* src = g_xh + ((size_t)b * SSQ + s0) * CCH;
        #pragma unroll
        for (int r = 0; r < 8; r++) {
            int id = tid + 256 * r;          // 0..2047
            int row = id >> 4, q = id & 15;
            *(uint4*)(Xs + row * 136 + q * 8) =
                *(const uint4*)(src + (size_t)row * CCH + q * 8);
        }
        const __half* sk = g_wkh + (size_t)(g * CCH + i1) * CCH;
        const __half* sv = g_wvh + (size_t)(g * CCH + i1) * CCH;
        #pragma unroll
        for (int r = 0; r < 4; r++) {
            int id = tid + 256 * r;          // 0..1023
            int row = id >> 4, q = id & 15;
            *(uint4*)(Wk + row * 136 + q * 8) = *(const uint4*)(sk + (size_t)row * CCH + q * 8);
            *(uint4*)(Wv + row * 136 + q * 8) = *(const uint4*)(sv + (size_t)row * CCH + q * 8);
        }
    }
    __syncthreads();

    // ---- K = Wk @ X^T ----
    float cK[8][4] = {};
    {
        const __half* A = Wk + (mt * 16) * 136;
        #pragma unroll
        for (int kk = 0; kk < 8; kk++) {
            uint32_t a0 = ldh2(A + gr * 136 + kk*16 + tc*2);
            uint32_t a1 = ldh2(A + (gr+8) * 136 + kk*16 + tc*2);
            uint32_t a2 = ldh2(A + gr * 136 + kk*16 + tc*2 + 8);
            uint32_t a3 = ldh2(A + (gr+8) * 136 + kk*16 + tc*2 + 8);
            #pragma unroll
            for (int nt = 0; nt < 8; nt++) {
                const __half* Bp = Xs + (nh*64 + nt*8 + gr) * 136 + kk*16 + tc*2;
                uint32_t b0 = ldh2(Bp), b1 = ldh2(Bp + 8);
                mma16816(cK[nt][0], cK[nt][1], cK[nt][2], cK[nt][3],
                         a0, a1, a2, a3, b0, b1);
            }
        }
    }
    #pragma unroll
    for (int nt = 0; nt < 8; nt++) {
        int sl = nh*64 + nt*8 + tc*2;
        int il = mt*16 + gr;
        St[sl * 72 + il]       = __float2half(cK[nt][0]);
        St[(sl+1) * 72 + il]   = __float2half(cK[nt][1]);
        St[sl * 72 + il + 8]   = __float2half(cK[nt][2]);
        St[(sl+1) * 72 + il+8] = __float2half(cK[nt][3]);
    }
    __syncthreads();
    {
        __half* kout = g_kh + (size_t)gb * SSQ * CCH;
        #pragma unroll
        for (int r = 0; r < 4; r++) {
            int id = tid + 256 * r;          // 0..1023
            int row = id >> 3, q = id & 7;
            *(uint4*)(kout + (size_t)(s0 + row) * CCH + i1 + q * 8) =
                *(const uint4*)(St + row * 72 + q * 8);
        }
    }

    // ---- V = Wv @ X^T ----
    float cV[8][4] = {};
    {
        const __half* A = Wv + (mt * 16) * 136;
        #pragma unroll
        for (int kk = 0; kk < 8; kk++) {
            uint32_t a0 = ldh2(A + gr * 136 + kk*16 + tc*2);
            uint32_t a1 = ldh2(A + (gr+8) * 136 + kk*16 + tc*2);
            uint32_t a2 = ldh2(A + gr * 136 + kk*16 + tc*2 + 8);
            uint32_t a3 = ldh2(A + (gr+8) * 136 + kk*16 + tc*2 + 8);
            #pragma unroll
            for (int nt = 0; nt < 8; nt++) {
                const __half* Bp = Xs + (nh*64 + nt*8 + gr) * 136 + kk*16 + tc*2;
                uint32_t b0 = ldh2(Bp), b1 = ldh2(Bp + 8);
                mma16816(cV[nt][0], cV[nt][1], cV[nt][2], cV[nt][3],
                         a0, a1, a2, a3, b0, b1);
            }
        }
    }
    __syncthreads();
    #pragma unroll
    for (int nt = 0; nt < 8; nt++) {
        int sl = nh*64 + nt*8 + tc*2;
        int il = mt*16 + gr;
        *(__half2*)(St + il * 136 + sl)       = __floats2half2_rn(cV[nt][0], cV[nt][1]);
        *(__half2*)(St + (il+8) * 136 + sl)   = __floats2half2_rn(cV[nt][2], cV[nt][3]);
    }
    __syncthreads();
    {
        __half* vout = g_vh + (size_t)gb * CCH * SSQ;
        #pragma unroll
        for (int r = 0; r < 4; r++) {
            int id = tid + 256 * r;          // 0..1023
            int row = id >> 4, q = id & 15;
            *(uint4*)(vout + (size_t)(i1 + row) * SSQ + s0 + q * 8) =
                *(const uint4*)(St + row * 136 + q * 8);
        }
    }
}

// ---------------------------------------------------------------------------
// Fused flash attention. One CTA per (g,b,h,p,lc), 32 L-rows, 8 warps.
// Per-pair K/V slice loads + named barriers; ILP-restructured st-body:
// 16 QK mma -> 16 exp -> 10 PV mma (incl. Z ones-row).
#define AT_K     0
#define AT_V     20480
#define AT_E     42240
#define AT_OUT   108288
#define AT_ZS    112512
#define AT_IZ    112640
#define AT_RED   112768
#define AT_TOT   112800
#define KBUF_H   5120     // K buffer stride (halfs) = 128*40
#define VBUF_H   5440     // V buffer stride (halfs) = 40*136
#define EST      1032
#define KST      40
#define VST      136

__global__ void __launch_bounds__(256, 2) attn_kernel() {
    extern __shared__ char smraw[];
    __half* Kb   = (__half*)(smraw + AT_K);
    __half* Vb   = (__half*)(smraw + AT_V);
    __half* E    = (__half*)(smraw + AT_E);
    float* out_sf= (float*)(smraw + AT_OUT);   // [32][33]
    float* zsh   = (float*)(smraw + AT_ZS);
    float* iz    = (float*)(smraw + AT_IZ);
    float* red   = (float*)(smraw + AT_RED);

    int idx = blockIdx.x;                  // 1536 = g(3) b(8) h(4) p(8) lc(2)
    int lc = idx & 1, p = (idx >> 1) & 7, h = (idx >> 4) & 3,
        b = (idx >> 6) & 7, g = idx >> 9;
    int tid = threadIdx.x, lane = tid & 31, w = tid >> 5;
    int gr = lane >> 2, tc = lane & 3;
    int lbase = lc * 32;

    const __half* Kg = g_kh + (size_t)(g*BB + b) * SSQ * CCH + h * DH;   // [s][128]+off
    const __half* Vg = g_vh + ((size_t)((g*BB + b) * CCH) + h * DH) * SSQ;
    const float*  Qg = g_q  + (size_t)(g*PP + p) * LLQ * CCH;

    int mh = w >> 2;                       // row half: rows mh*16..+16
    int ng = w & 3;                        // s-block of 32 within 128-s tile
    int plid = mh * 32 + lane;             // pair-local index 0..63
    int r_lo = mh * 16 + gr, r_hi = r_lo + 8;

    // zero reduction buffers
    #pragma unroll
    for (int r = 0; r < 5; r++) {
        int id = tid + 256 * r;
        if (id < 1056) out_sf[id] = 0.f;
    }
    if (tid < 32) zsh[tid] = 0.f;
    // init V extra rows (32 = ones, 33..39 = zeros) in BOTH buffers
    for (int id = tid; id < 2 * 8 * VST; id += 256) {
        int buf = id / (8 * VST);
        int rem = id - buf * 8 * VST;
        int rrow = rem / VST, cc = rem % VST;
        Vb[buf * VBUF_H + (32 + rrow) * VST + cc] =
            (rrow == 0) ? __float2half(1.f) : __float2half(0.f);
    }

    // A fragments for QK from global q (fp32 -> half2)
    uint32_t aq[2][4];
    {
        const float* q0 = Qg + (size_t)(lbase + r_lo) * CCH + h * DH;
        const float* q1 = q0 + 8 * CCH;
        #pragma unroll
        for (int ks = 0; ks < 2; ks++) {
            float2 f0 = *(const float2*)(q0 + ks*16 + tc*2);
            float2 f1 = *(const float2*)(q1 + ks*16 + tc*2);
            float2 f2 = *(const float2*)(q0 + ks*16 + tc*2 + 8);
            float2 f3 = *(const float2*)(q1 + ks*16 + tc*2 + 8);
            aq[ks][0] = packh2(f0.x, f0.y);
            aq[ks][1] = packh2(f1.x, f1.y);
            aq[ks][2] = packh2(f2.x, f2.y);
            aq[ks][3] = packh2(f3.x, f3.y);
        }
    }

    // Per-pair slice loads: pair ng loads K rows [ng*32,+32) and V cols [ng*32,+32).
    auto loadK = [&](int st, int bf) {
        const __half* src = Kg + (size_t)st * 128 * CCH;
        __half* dst = Kb + bf * KBUF_H;
        #pragma unroll
        for (int it = 0; it < 2; it++) {
            int id = plid + 64 * it;       // 0..127
            int rl = ng*32 + (id >> 2), ch = id & 3;
            *(uint4*)(dst + rl * KST + ch * 8) =
                *(const uint4*)(src + (size_t)rl * CCH + ch * 8);
        }
    };
    auto loadV = [&](int st, int bf) {
        const __half* src = Vg + st * 128 + ng * 32;
        __half* dst = Vb + bf * VBUF_H + ng * 32;
        #pragma unroll
        for (int it = 0; it < 2; it++) {
            int id = plid + 64 * it;       // 0..127
            int d = id >> 2, ch = id & 3;
            *(uint4*)(dst + d * VST + ch * 8) =
                *(const uint4*)(src + (size_t)d * SSQ + ch * 8);
        }
    };

    loadK(0, 0);
    loadV(0, 0);
    __syncthreads();                       // init (ones rows etc.) + prologue visible

    float pv[5][4] = {};                   // nd 0..3: out tiles; nd 4: Z (ones row)

    for (int st = 0; st < 8; st++) {
        if (st > 0)
            asm volatile("bar.sync %0, 64;" :: "r"(ng + 1) : "memory");
        if (st < 7) { loadK(st + 1, (st + 1) & 1); loadV(st + 1, (st + 1) & 1); }
        const __half* Kt = Kb + (st & 1) * KBUF_H;
        const __half* Vt = Vb + (st & 1) * VBUF_H;

        // ---- QK: 4 independent C-tiles (16 mmas, 4-deep chains) ----
        float c[4][4] = {};
        #pragma unroll
        for (int nt = 0; nt < 4; nt++) {
            const __half* kb = Kt + (ng*32 + nt*8 + gr) * KST;
            #pragma unroll
            for (int ks = 0; ks < 2; ks++) {
                uint32_t b0 = ldh2(kb + ks*16 + tc*2);
                uint32_t b1 = ldh2(kb + ks*16 + tc*2 + 8);
                mma16816(c[nt][0], c[nt][1], c[nt][2], c[nt][3],
                         aq[ks][0], aq[ks][1], aq[ks][2], aq[ks][3], b0, b1);
            }
        }
        // ---- exp + pack + E store ----
        uint32_t af[4][2];
        #pragma unroll
        for (int nt = 0; nt < 4; nt++) {
            float e0 = __expf(c[nt][0] * SCALE_F), e1 = __expf(c[nt][1] * SCALE_F);
            float e2 = __expf(c[nt][2] * SCALE_F), e3 = __expf(c[nt][3] * SCALE_F);
            af[nt][0] = packh2(e0, e1);
            af[nt][1] = packh2(e2, e3);
            int scol = st*128 + ng*32 + nt*8 + tc*2;
            *(uint32_t*)&E[r_lo * EST + scol] = af[nt][0];
            *(uint32_t*)&E[r_hi * EST + scol] = af[nt][1];
        }
        // ---- PV + Z: nd 0..3 = out, nd 4 hits the ones row (d=32) ----
        #pragma unroll
        for (int j = 0; j < 2; j++) {
            int sloc = ng*32 + j*16 + tc*2;
            #pragma unroll
            for (int nd = 0; nd < 5; nd++) {
                const __half* vbp = Vt + (nd*8 + gr) * VST + sloc;
                uint32_t b0 = ldh2(vbp);
                uint32_t b1 = ldh2(vbp + 8);
                mma16816(pv[nd][0], pv[nd][1], pv[nd][2], pv[nd][3],
                         af[2*j][0], af[2*j][1], af[2*j+1][0], af[2*j+1][1], b0, b1);
            }
        }
    }

    // ---- Z: pv[4][0]/[2] at tc==0 hold row sums over this warp's s-slice ----
    if (tc == 0) {
        atomicAdd(&zsh[r_lo], pv[4][0]);
        atomicAdd(&zsh[r_hi], pv[4][2]);
    }
    // ---- out partial reduction across ng-warps ----
    #pragma unroll
    for (int nd = 0; nd < 4; nd++) {
        int d = nd*8 + tc*2;
        atomicAdd(&out_sf[r_lo*33 + d],     pv[nd][0]);
        atomicAdd(&out_sf[r_lo*33 + d + 1], pv[nd][1]);
        atomicAdd(&out_sf[r_hi*33 + d],     pv[nd][2]);
        atomicAdd(&out_sf[r_hi*33 + d + 1], pv[nd][3]);
    }
    __syncthreads();                       // E complete + zsh/out atomics done
    if (tid < 32) iz[tid] = 1.f / zsh[tid];
    __syncthreads();

    // ---- heat (uint2 loads: 4 s-columns per thread) ----
    float* hout = g_heat + (size_t)((g*BB + b) * PP + p) * SSQ;
    {
        int scol = tid * 4;
        float hs0 = 0.f, hs1 = 0.f, hs2 = 0.f, hs3 = 0.f;
        #pragma unroll
        for (int r = 0; r < 32; r++) {
            uint2 u = *(const uint2*)&E[r * EST + scol];
            float2 fa = __half22float2(reinterpret_cast<__half2&>(u.x));
            float2 fb = __half22float2(reinterpret_cast<__half2&>(u.y));
            float izr = iz[r];
            hs0 += fa.x * izr; hs1 += fa.y * izr;
            hs2 += fb.x * izr; hs3 += fb.y * izr;
        }
        atomicAdd(&hout[scol],     hs0);
        atomicAdd(&hout[scol + 1], hs1);
        atomicAdd(&hout[scol + 2], hs2);
        atomicAdd(&hout[scol + 3], hs3);
    }

    // ---- dist ----
    float dacc = 0.f;
    #pragma unroll
    for (int r = 0; r < 4; r++) {
        int id = tid + 256 * r;            // 0..1023
        int row = id >> 5, d = id & 31;
        float o = out_sf[row*33 + d] * iz[row];
        float qv = Qg[(size_t)(lbase + row) * CCH + h * DH + d];
        float e = qv - o;
        dacc += e * e;
    }
    #pragma unroll
    for (int o = 16; o; o >>= 1) dacc += __shfl_xor_sync(0xffffffffu, dacc, o);
    if (lane == 0) red[w] = dacc;
    __syncthreads();
    if (w == 0) {
        float v = (lane < 8) ? red[lane] : 0.f;
        #pragma unroll
        for (int o = 4; o; o >>= 1) v += __shfl_xor_sync(0xffffffffu, v, o);
        if (lane == 0) atomicAdd(&g_dist[(g*BB + b) * PP + p], v);
    }
}

// ---------------------------------------------------------------------------
// Finalize: dist/(64*128) and argmax(heat) -> out = [dist(8x24) | idx(8x24)]
__global__ void finalize_kernel(float* __restrict__ out, int out_size) {
    __shared__ float bv[128];
    __shared__ int  bidx[128];
    int gbp = blockIdx.x;
    int tid = threadIdx.x;
    const float* hrow = g_heat + (size_t)gbp * SSQ;
    float best = -1e30f; int bi = 0;
    for (int j = tid; j < SSQ; j += 128) {
        float v = hrow[j];
        if (v > best) { best = v; bi = j; }
    }
    bv[tid] = best; bidx[tid] = bi;
    __syncthreads();
    for (int s = 64; s; s >>= 1) {
        if (tid < s) {
            if (bv[tid + s] > bv[tid] ||
                (bv[tid + s] == bv[tid] && bidx[tid + s] < bidx[tid])) {
                bv[tid] = bv[tid + s]; bidx[tid] = bidx[tid + s];
            }
        }
        __syncthreads();
    }
    if (tid == 0) {
        int g = gbp >> 6, b = (gbp >> 3) & 7, p = gbp & 7;
        int col = g * PP + p;
        out[b * 24 + col] = g_dist[gbp] * (1.f / (64.f * 128.f));
        if (out_size >= 384)
            out[192 + b * 24 + col] = (float)bidx[0];
    }
}

// ---------------------------------------------------------------------------
extern "C" void kernel_launch(void* const* d_in, const int* in_sizes, int n_in,
                              void* d_out, int out_size) {
    const float* x     = (const float*)d_in[0];
    const float* proto = (const float*)d_in[1];
    const float* qw    = (const float*)d_in[2];
    const float* kw    = (const float*)d_in[3];
    const float* vw    = (const float*)d_in[4];
    float* out = (float*)d_out;

    cudaFuncSetAttribute(attn_kernel,
                         cudaFuncAttributeMaxDynamicSharedMemorySize, AT_TOT);
    cudaFuncSetAttribute(proj_kv_mma_kernel,
                         cudaFuncAttributeMaxDynamicSharedMemorySize, PJ_TOT);
    cudaFuncSetAttribute(fused_pre_kernel,
                         cudaFuncAttributeMaxDynamicSharedMemorySize, FP_TOT);

    fused_pre_kernel<<<1120, 256, FP_TOT>>>(x, proto, qw, kw, vw);
    proj_kv_mma_kernel<<<dim3(8, 2, 24), 256, PJ_TOT>>>();
    attn_kernel<<<1536, 256, AT_TOT>>>();
    finalize_kernel<<<192, 128>>>(out, out_size);
}